// round 6
// baseline (speedup 1.0000x reference)
#include <cuda_runtime.h>
#include <cuda_bf16.h>
#include <cuda_fp16.h>
#include <cstdint>

#define BATCH 2
#define CHW   64
#define DDIM  64
#define NTOK  8192
#define HW    1024
#define TDIM  8
#define NIT   64         // key blocks of 128
#define ROWB  144        // 144 B smem row stride (72 halfwords)
#define QSCALE 0.180336880111120426f   // 0.125 * log2(e): softmax in base-2

// -------- global scratch (allocations forbidden) --------
__device__ __align__(256) __nv_bfloat16 g_q[BATCH * NTOK * DDIM];  // pre-scaled by QSCALE
__device__ __align__(256) __nv_bfloat16 g_k[BATCH * NTOK * DDIM];
__device__ __align__(256) __half        g_v[BATCH * NTOK * DDIM];
__device__ __align__(256) float         g_o[BATCH * NTOK * DDIM];
__device__ __align__(256) __nv_bfloat16 g_wb[3 * DDIM * CHW];      // bf16 W (wq pre-scaled)
__device__ __align__(256) float         g_bias[3 * DDIM];          // bq pre-scaled

// ---------------- helpers ----------------
__device__ __forceinline__ uint32_t smem_u32(const void* p) {
    uint32_t a;
    asm("{ .reg .u64 t; cvta.to.shared.u64 t, %1; cvt.u32.u64 %0, t; }" : "=r"(a) : "l"(p));
    return a;
}
__device__ __forceinline__ void cp16(uint32_t saddr, const void* gaddr) {
    asm volatile("cp.async.cg.shared.global [%0], [%1], 16;" :: "r"(saddr), "l"(gaddr) : "memory");
}
#define CP_COMMIT() asm volatile("cp.async.commit_group;" ::: "memory")
#define CP_WAIT(n)  asm volatile("cp.async.wait_group %0;" :: "n"(n) : "memory")

__device__ __forceinline__ void ldsm_x4(uint32_t* r, uint32_t a) {
    asm volatile("ldmatrix.sync.aligned.m8n8.x4.shared.b16 {%0,%1,%2,%3}, [%4];"
                 : "=r"(r[0]), "=r"(r[1]), "=r"(r[2]), "=r"(r[3]) : "r"(a));
}
__device__ __forceinline__ void ldsm_x4_t(uint32_t* r, uint32_t a) {
    asm volatile("ldmatrix.sync.aligned.m8n8.x4.trans.shared.b16 {%0,%1,%2,%3}, [%4];"
                 : "=r"(r[0]), "=r"(r[1]), "=r"(r[2]), "=r"(r[3]) : "r"(a));
}
__device__ __forceinline__ void mma_bf16(float* c, const uint32_t* a, uint32_t b0, uint32_t b1) {
    asm volatile(
        "mma.sync.aligned.m16n8k16.row.col.f32.bf16.bf16.f32 "
        "{%0,%1,%2,%3}, {%4,%5,%6,%7}, {%8,%9}, {%0,%1,%2,%3};"
        : "+f"(c[0]), "+f"(c[1]), "+f"(c[2]), "+f"(c[3])
        : "r"(a[0]), "r"(a[1]), "r"(a[2]), "r"(a[3]), "r"(b0), "r"(b1));
}
__device__ __forceinline__ void mma_f16(float* c, const uint32_t* a, uint32_t b0, uint32_t b1) {
    asm volatile(
        "mma.sync.aligned.m16n8k16.row.col.f32.f16.f16.f32 "
        "{%0,%1,%2,%3}, {%4,%5,%6,%7}, {%8,%9}, {%0,%1,%2,%3};"
        : "+f"(c[0]), "+f"(c[1]), "+f"(c[2]), "+f"(c[3])
        : "r"(a[0]), "r"(a[1]), "r"(a[2]), "r"(a[3]), "r"(b0), "r"(b1));
}
__device__ __forceinline__ uint32_t pack_bf16(float lo, float hi) {
    uint32_t r;
    asm("cvt.rn.bf16x2.f32 %0, %1, %2;" : "=r"(r) : "f"(hi), "f"(lo));
    return r;
}
__device__ __forceinline__ uint32_t pack_f16(float lo, float hi) {
    uint32_t r;
    asm("cvt.rn.f16x2.f32 %0, %1, %2;" : "=r"(r) : "f"(hi), "f"(lo));
    return r;
}
__device__ __forceinline__ uint32_t ex2_h2(uint32_t a) {
    uint32_t r;
    asm("ex2.approx.f16x2 %0, %1;" : "=r"(r) : "r"(a));
    return r;
}
__device__ __forceinline__ uint32_t hadd2(uint32_t a, uint32_t b) {
    uint32_t r;
    asm("add.rn.f16x2 %0, %1, %2;" : "=r"(r) : "r"(a), "r"(b));
    return r;
}
__device__ __forceinline__ float2 h2_to_f2(uint32_t h) {
    __half2 v = *(__half2*)&h;
    return make_float2(__low2float(v), __high2float(v));
}

// ---------------------------------------------------------------------------
// Kernel 0: one-time W/bias convert (wq, bq pre-scaled by QSCALE)
// ---------------------------------------------------------------------------
__global__ __launch_bounds__(256) void setup_kernel(
    const float* __restrict__ wq, const float* __restrict__ bq,
    const float* __restrict__ wk, const float* __restrict__ bk,
    const float* __restrict__ wv, const float* __restrict__ bv)
{
    int idx = blockIdx.x * 256 + threadIdx.x;
    if (idx < 3 * DDIM * CHW) {
        int m = idx >> 12, rc = idx & 4095;
        const float* W = (m == 0) ? wq : (m == 1) ? wk : wv;
        float sc = (m == 0) ? QSCALE : 1.0f;
        g_wb[idx] = __float2bfloat16_rn(W[rc] * sc);
    }
    if (idx < 3 * DDIM) {
        int m = idx >> 6;
        const float* Bp = (m == 0) ? bq : (m == 1) ? bk : bv;
        g_bias[idx] = Bp[idx & 63] * ((m == 0) ? QSCALE : 1.0f);
    }
}

// ---------------------------------------------------------------------------
// Kernel 1: QKV projection on HMMA. 64-token CTAs, grid 256, 128 threads,
// 2 CTAs/SM. W loaded pre-converted via cp.async.
// ---------------------------------------------------------------------------
#define PQX 0                    // fp32 x [64 c][66 n]  (16896 B)
#define PXB 16896                // bf16 x^T [64 n][72 c] rows 144 B (9216 B)
#define PWB 26112                // bf16 W [3][64 d][72 c] rows 144 B (27648 B)
#define PBI 53760                // fp32 bias [3][64] (768 B)
#define PSM 54528

__global__ __launch_bounds__(128, 2) void proj_kernel(const float* __restrict__ x)
{
    extern __shared__ char psm[];
    float* xsf = (float*)psm;
    const uint32_t sb = smem_u32(psm);

    const int tid  = threadIdx.x;
    const int w    = tid >> 5;
    const int lane = tid & 31;
    const int g    = lane >> 2;
    const int tc   = lane & 3;
    const int b    = blockIdx.x >> 7;
    const int n0   = (blockIdx.x & 127) * 64;

    // W (bf16) + bias via cp.async (1536 + 48 chunks)
    #pragma unroll
    for (int j = 0; j < 12; j++) {
        int c = tid + j * 128;                 // 0..1535
        int rrow = c >> 3, c8 = c & 7;
        cp16(sb + PWB + rrow * 144 + c8 * 16, (const char*)g_wb + rrow * 128 + c8 * 16);
    }
    if (tid < 48) cp16(sb + PBI + tid * 16, (const char*)g_bias + tid * 16);
    CP_COMMIT();

    // x tile fp32, coalesced
    #pragma unroll
    for (int i = tid, j = 0; j < 32; j++, i += 128) {
        int c = i >> 6, n = i & 63;
        xsf[c * 66 + n] = x[((size_t)b * CHW + c) * NTOK + n0 + n];
    }
    __syncthreads();

    // transpose-convert x -> bf16 [n][c]
    {
        int n = tid & 63, ch = (tid >> 6) * 32;
        uint32_t u[16];
        #pragma unroll
        for (int j = 0; j < 16; j++)
            u[j] = pack_bf16(xsf[(ch + 2*j) * 66 + n], xsf[(ch + 2*j + 1) * 66 + n]);
        uint4* d4 = (uint4*)(psm + PXB + n * 144 + ch * 2);
        #pragma unroll
        for (int j = 0; j < 4; j++)
            d4[j] = make_uint4(u[4*j], u[4*j+1], u[4*j+2], u[4*j+3]);
    }
    CP_WAIT(0);
    __syncthreads();

    uint32_t af[4][4];
    {
        uint32_t arow = sb + PXB + (w * 16 + (lane & 15)) * 144 + (lane >> 4) * 16;
        #pragma unroll
        for (int kc = 0; kc < 4; kc++)
            ldsm_x4(af[kc], arow + kc * 32);
    }

    const float* biasf = (const float*)(psm + PBI);
    const uint32_t wrow = sb + PWB + (lane & 15) * 144 + (lane >> 4) * 16;

    #pragma unroll
    for (int m = 0; m < 3; m++) {
        float acc[4][2][4];
        #pragma unroll
        for (int i = 0; i < 4; i++)
            #pragma unroll
            for (int s2 = 0; s2 < 2; s2++)
                #pragma unroll
                for (int j = 0; j < 4; j++) acc[i][s2][j] = 0.f;

        #pragma unroll
        for (int nth = 0; nth < 4; nth++) {
            #pragma unroll
            for (int kc = 0; kc < 4; kc++) {
                uint32_t bf[4];
                ldsm_x4(bf, wrow + m * 9216 + nth * 16 * 144 + kc * 32);
                mma_bf16(acc[nth][0], af[kc], bf[0], bf[2]);
                mma_bf16(acc[nth][1], af[kc], bf[1], bf[3]);
            }
        }

        const size_t r0 = (size_t)(b * NTOK + n0 + w * 16 + g) * DDIM;
        const size_t r1 = r0 + 8 * DDIM;
        #pragma unroll
        for (int nth = 0; nth < 4; nth++) {
            #pragma unroll
            for (int s2 = 0; s2 < 2; s2++) {
                int d0 = nth * 16 + s2 * 8 + 2 * tc;
                float bb0 = biasf[m * 64 + d0], bb1 = biasf[m * 64 + d0 + 1];
                float v00 = acc[nth][s2][0] + bb0, v01 = acc[nth][s2][1] + bb1;
                float v10 = acc[nth][s2][2] + bb0, v11 = acc[nth][s2][3] + bb1;
                if (m < 2) {
                    __nv_bfloat16* dst = (m == 0) ? g_q : g_k;
                    *(uint32_t*)(dst + r0 + d0) = pack_bf16(v00, v01);
                    *(uint32_t*)(dst + r1 + d0) = pack_bf16(v10, v11);
                } else {
                    *(uint32_t*)(g_v + r0 + d0) = pack_f16(v00, v01);
                    *(uint32_t*)(g_v + r1 + d0) = pack_f16(v10, v11);
                }
            }
        }
    }
}

// ---------------------------------------------------------------------------
// Kernel 2: FA2 attention. 64 q-rows / 128 threads per CTA, grid 256,
// 2 CTAs/SM (independent CTAs overlap each other's barrier/exp windows).
// smem: Q[64][72] + K[2][128][72] + V[2][128][72] = 82944 B
// ---------------------------------------------------------------------------
#define SQ  0
#define SK  9216
#define SV  (9216 + 36864)
#define SM_DYN (9216 + 73728)

__device__ __forceinline__ void prefetch_kv(uint32_t sb, int b, int it, int p, int tid) {
    const uint4* ks = (const uint4*)(g_k + ((size_t)(b * NTOK + it * 128)) * DDIM);
    const uint4* vs = (const uint4*)(g_v + ((size_t)(b * NTOK + it * 128)) * DDIM);
    #pragma unroll
    for (int c = tid, j = 0; j < 8; j++, c += 128) {
        int r = c >> 3, c8 = c & 7;
        uint32_t off = r * ROWB + c8 * 16;
        cp16(sb + SK + p * 18432 + off, ks + c);
        cp16(sb + SV + p * 18432 + off, vs + c);
    }
    CP_COMMIT();
}

__global__ __launch_bounds__(128, 2) void attn_kernel()
{
    extern __shared__ char smc[];
    const uint32_t sb = smem_u32(smc);

    const int tid  = threadIdx.x;
    const int w    = tid >> 5;
    const int lane = tid & 31;
    const int g    = lane >> 2;
    const int tc   = lane & 3;
    const int b    = blockIdx.x >> 7;
    const int n0   = (blockIdx.x & 127) * 64;

    prefetch_kv(sb, b, 0, 0, tid);

    {
        const uint4* src = (const uint4*)(g_q + ((size_t)(b * NTOK + n0)) * DDIM);
        #pragma unroll
        for (int c = tid, j = 0; j < 4; j++, c += 128) {
            int r = c >> 3, c8 = c & 7;
            *(uint4*)(smc + SQ + r * ROWB + c8 * 16) = src[c];
        }
    }
    __syncthreads();

    uint32_t qa[4][4];
    {
        uint32_t rowaddr = sb + SQ + (w * 16 + (lane & 15)) * ROWB + (lane >> 4) * 16;
        #pragma unroll
        for (int kc = 0; kc < 4; kc++)
            ldsm_x4(qa[kc], rowaddr + kc * 32);
    }

    float Oc[8][4];
    #pragma unroll
    for (int i = 0; i < 8; i++)
        #pragma unroll
        for (int j = 0; j < 4; j++) Oc[i][j] = 0.f;
    float ls0 = 0.f, ls1 = 0.f;

    for (int it = 0; it < NIT; it++) {
        const int p = it & 1;
        if (it + 1 < NIT) { prefetch_kv(sb, b, it + 1, p ^ 1, tid); CP_WAIT(1); }
        else              { CP_WAIT(0); }
        __syncthreads();

        const uint32_t kb = sb + SK + p * 18432;
        const uint32_t vb = sb + SV + p * 18432;
        const uint32_t lrow = (lane & 15) * ROWB + (lane >> 4) * 16;

        // ---- S(16x128) = Q * K^T (log2-domain) ----
        float S[16][4];
        #pragma unroll
        for (int nth = 0; nth < 8; nth++) {
            #pragma unroll
            for (int j = 0; j < 4; j++) { S[2*nth][j] = 0.f; S[2*nth+1][j] = 0.f; }
            #pragma unroll
            for (int kc = 0; kc < 4; kc++) {
                uint32_t kf[4];
                ldsm_x4(kf, kb + nth * 16 * ROWB + lrow + kc * 32);
                mma_bf16(S[2*nth],     qa[kc], kf[0], kf[2]);
                mma_bf16(S[2*nth + 1], qa[kc], kf[1], kf[3]);
            }
        }

        // ---- fused exp + PV per 16-key chunk ----
        uint32_t s0a = 0u, s1a = 0u;
        #pragma unroll
        for (int kc2 = 0; kc2 < 8; kc2++) {
            uint32_t pab[4];
            pab[0] = ex2_h2(pack_f16(S[2*kc2][0],   S[2*kc2][1]));
            pab[1] = ex2_h2(pack_f16(S[2*kc2][2],   S[2*kc2][3]));
            pab[2] = ex2_h2(pack_f16(S[2*kc2+1][0], S[2*kc2+1][1]));
            pab[3] = ex2_h2(pack_f16(S[2*kc2+1][2], S[2*kc2+1][3]));
            s0a = hadd2(hadd2(s0a, pab[0]), pab[2]);
            s1a = hadd2(hadd2(s1a, pab[1]), pab[3]);
            #pragma unroll
            for (int ntp = 0; ntp < 4; ntp++) {
                uint32_t vf[4];
                ldsm_x4_t(vf, vb + kc2 * 16 * ROWB + lrow + ntp * 32);
                mma_f16(Oc[2*ntp],     pab, vf[0], vf[1]);
                mma_f16(Oc[2*ntp + 1], pab, vf[2], vf[3]);
            }
        }
        {
            float2 f0 = h2_to_f2(s0a), f1 = h2_to_f2(s1a);
            ls0 += f0.x + f0.y;
            ls1 += f1.x + f1.y;
        }
        __syncthreads();
    }

    // ---- epilogue ----
    ls0 += __shfl_xor_sync(0xffffffffu, ls0, 1);
    ls0 += __shfl_xor_sync(0xffffffffu, ls0, 2);
    ls1 += __shfl_xor_sync(0xffffffffu, ls1, 1);
    ls1 += __shfl_xor_sync(0xffffffffu, ls1, 2);
    const float inv0 = 1.0f / ls0, inv1 = 1.0f / ls1;

    float* o0 = g_o + ((size_t)(b * NTOK + n0 + w * 16 + g)) * DDIM;
    float* o1 = o0 + 8 * DDIM;
    #pragma unroll
    for (int nt = 0; nt < 8; nt++) {
        int col = nt * 8 + 2 * tc;
        *(float2*)(o0 + col) = make_float2(Oc[nt][0] * inv0, Oc[nt][1] * inv0);
        *(float2*)(o1 + col) = make_float2(Oc[nt][2] * inv1, Oc[nt][3] * inv1);
    }
}

// ---------------------------------------------------------------------------
// Kernel 3: coalesced t-reduction
// ---------------------------------------------------------------------------
__global__ __launch_bounds__(256) void reduce_kernel(float* __restrict__ out)
{
    __shared__ float sm[DDIM][33];
    const int b   = blockIdx.x >> 5;
    const int yx0 = (blockIdx.x & 31) * 32;
    const int tid = threadIdx.x;
    const int dd  = tid & 63;
    const int q   = tid >> 6;

    for (int yl = q; yl < 32; yl += 4) {
        float acc = 0.f;
        #pragma unroll
        for (int t = 0; t < TDIM; t++)
            acc += g_o[((size_t)(b * NTOK + t * HW + yx0 + yl)) * DDIM + dd];
        sm[dd][yl] = acc;
    }
    __syncthreads();

    for (int i = tid; i < DDIM * 32; i += 256) {
        int d2 = i >> 5, yxl = i & 31;
        out[(size_t)b * (DDIM * HW) + d2 * HW + yx0 + yxl] = sm[d2][yxl];
    }
}

// ---------------------------------------------------------------------------
extern "C" void kernel_launch(void* const* d_in, const int* in_sizes, int n_in,
                              void* d_out, int out_size)
{
    const float* x  = (const float*)d_in[0];
    const float* wq = (const float*)d_in[1];
    const float* bq = (const float*)d_in[2];
    const float* wk = (const float*)d_in[3];
    const float* bk = (const float*)d_in[4];
    const float* wv = (const float*)d_in[5];
    const float* bv = (const float*)d_in[6];

    cudaFuncSetAttribute(proj_kernel,
                         cudaFuncAttributeMaxDynamicSharedMemorySize, PSM);
    cudaFuncSetAttribute(attn_kernel,
                         cudaFuncAttributeMaxDynamicSharedMemorySize, SM_DYN);

    setup_kernel<<<48, 256>>>(wq, bq, wk, bk, wv, bv);
    proj_kernel<<<BATCH * (NTOK / 64), 128, PSM>>>(x);
    attn_kernel<<<BATCH * (NTOK / 64), 128, SM_DYN>>>();
    reduce_kernel<<<BATCH * (HW / 32), 256>>>((float*)d_out);
}

// round 7
// speedup vs baseline: 1.5469x; 1.5469x over previous
#include <cuda_runtime.h>
#include <cuda_bf16.h>
#include <cuda_fp16.h>
#include <cstdint>

#define BATCH 2
#define CHW   64
#define DDIM  64
#define NTOK  8192
#define HW    1024
#define TDIM  8
#define NIT   64         // key blocks of 128
#define ROWB  144        // 144 B smem row stride (72 halfwords)
#define QSCALE 0.180336880111120426f   // 0.125 * log2(e): softmax in base-2

// -------- global scratch (allocations forbidden) --------
__device__ __align__(256) __nv_bfloat16 g_q [BATCH * NTOK * DDIM];  // pre-scaled by QSCALE
__device__ __align__(256) __nv_bfloat16 g_k [BATCH * NTOK * DDIM];
__device__ __align__(256) __half        g_v [BATCH * NTOK * DDIM];
__device__ __align__(256) float         g_ot[BATCH * DDIM * NTOK];  // O transposed [b][d][n]
__device__ __align__(256) __nv_bfloat16 g_wb[3 * DDIM * CHW];       // bf16 W (wq pre-scaled)
__device__ __align__(256) float         g_bias[3 * DDIM];           // bq pre-scaled

// ---------------- helpers ----------------
__device__ __forceinline__ uint32_t smem_u32(const void* p) {
    uint32_t a;
    asm("{ .reg .u64 t; cvta.to.shared.u64 t, %1; cvt.u32.u64 %0, t; }" : "=r"(a) : "l"(p));
    return a;
}
__device__ __forceinline__ void cp16(uint32_t saddr, const void* gaddr) {
    asm volatile("cp.async.cg.shared.global [%0], [%1], 16;" :: "r"(saddr), "l"(gaddr) : "memory");
}
#define CP_COMMIT() asm volatile("cp.async.commit_group;" ::: "memory")
#define CP_WAIT(n)  asm volatile("cp.async.wait_group %0;" :: "n"(n) : "memory")

__device__ __forceinline__ void ldsm_x4(uint32_t* r, uint32_t a) {
    asm volatile("ldmatrix.sync.aligned.m8n8.x4.shared.b16 {%0,%1,%2,%3}, [%4];"
                 : "=r"(r[0]), "=r"(r[1]), "=r"(r[2]), "=r"(r[3]) : "r"(a));
}
__device__ __forceinline__ void ldsm_x4_t(uint32_t* r, uint32_t a) {
    asm volatile("ldmatrix.sync.aligned.m8n8.x4.trans.shared.b16 {%0,%1,%2,%3}, [%4];"
                 : "=r"(r[0]), "=r"(r[1]), "=r"(r[2]), "=r"(r[3]) : "r"(a));
}
__device__ __forceinline__ void mma_bf16(float* c, const uint32_t* a, uint32_t b0, uint32_t b1) {
    asm volatile(
        "mma.sync.aligned.m16n8k16.row.col.f32.bf16.bf16.f32 "
        "{%0,%1,%2,%3}, {%4,%5,%6,%7}, {%8,%9}, {%0,%1,%2,%3};"
        : "+f"(c[0]), "+f"(c[1]), "+f"(c[2]), "+f"(c[3])
        : "r"(a[0]), "r"(a[1]), "r"(a[2]), "r"(a[3]), "r"(b0), "r"(b1));
}
__device__ __forceinline__ void mma_f16(float* c, const uint32_t* a, uint32_t b0, uint32_t b1) {
    asm volatile(
        "mma.sync.aligned.m16n8k16.row.col.f32.f16.f16.f32 "
        "{%0,%1,%2,%3}, {%4,%5,%6,%7}, {%8,%9}, {%0,%1,%2,%3};"
        : "+f"(c[0]), "+f"(c[1]), "+f"(c[2]), "+f"(c[3])
        : "r"(a[0]), "r"(a[1]), "r"(a[2]), "r"(a[3]), "r"(b0), "r"(b1));
}
__device__ __forceinline__ uint32_t pack_bf16(float lo, float hi) {
    uint32_t r;
    asm("cvt.rn.bf16x2.f32 %0, %1, %2;" : "=r"(r) : "f"(hi), "f"(lo));
    return r;
}
__device__ __forceinline__ uint32_t pack_f16(float lo, float hi) {
    uint32_t r;
    asm("cvt.rn.f16x2.f32 %0, %1, %2;" : "=r"(r) : "f"(hi), "f"(lo));
    return r;
}
__device__ __forceinline__ uint32_t ex2_h2(uint32_t a) {
    uint32_t r;
    asm("ex2.approx.f16x2 %0, %1;" : "=r"(r) : "r"(a));
    return r;
}
__device__ __forceinline__ uint32_t hadd2(uint32_t a, uint32_t b) {
    uint32_t r;
    asm("add.rn.f16x2 %0, %1, %2;" : "=r"(r) : "r"(a), "r"(b));
    return r;
}
__device__ __forceinline__ float2 h2_to_f2(uint32_t h) {
    __half2 v = *(__half2*)&h;
    return make_float2(__low2float(v), __high2float(v));
}

// ---------------------------------------------------------------------------
// Kernel 0: one-time W/bias convert (wq, bq pre-scaled by QSCALE)
// ---------------------------------------------------------------------------
__global__ __launch_bounds__(256) void setup_kernel(
    const float* __restrict__ wq, const float* __restrict__ bq,
    const float* __restrict__ wk, const float* __restrict__ bk,
    const float* __restrict__ wv, const float* __restrict__ bv)
{
    int idx = blockIdx.x * 256 + threadIdx.x;
    if (idx < 3 * DDIM * CHW) {
        int m = idx >> 12, rc = idx & 4095;
        const float* W = (m == 0) ? wq : (m == 1) ? wk : wv;
        float sc = (m == 0) ? QSCALE : 1.0f;
        g_wb[idx] = __float2bfloat16_rn(W[rc] * sc);
    }
    if (idx < 3 * DDIM) {
        int m = idx >> 6;
        const float* Bp = (m == 0) ? bq : (m == 1) ? bk : bv;
        g_bias[idx] = Bp[idx & 63] * ((m == 0) ? QSCALE : 1.0f);
    }
}

// ---------------------------------------------------------------------------
// Kernel 1: QKV projection on HMMA. grid 128 (b x 64 tiles of 128 tokens),
// 256 threads. W/bias pre-converted, pulled via cp.async.
// ---------------------------------------------------------------------------
#define PXF 0                    // fp32 x [64][132]          (33792 B)
#define PXB 33792                // bf16 x^T [128][72] 144B   (18432 B)
#define PWB 52224                // bf16 W [3][64][72] 144B   (27648 B)
#define PBI 79872                // fp32 bias [3][64]         (768 B)
#define PSM 80640

__global__ __launch_bounds__(256) void proj_kernel(const float* __restrict__ x)
{
    extern __shared__ char psm[];
    float* xsf = (float*)psm;
    const uint32_t sb = smem_u32(psm);

    const int tid  = threadIdx.x;
    const int w    = tid >> 5;
    const int lane = tid & 31;
    const int g    = lane >> 2;
    const int tc   = lane & 3;
    const int b    = blockIdx.x >> 6;
    const int n0   = (blockIdx.x & 63) * 128;

    // W (pre-converted bf16) + bias via cp.async
    #pragma unroll
    for (int j = 0; j < 6; j++) {
        int c = tid + j * 256;                 // 0..1535 16B chunks
        int rrow = c >> 3, c8 = c & 7;
        cp16(sb + PWB + rrow * 144 + c8 * 16, (const char*)g_wb + c * 16);
    }
    if (tid < 48) cp16(sb + PBI + tid * 16, (const char*)g_bias + tid * 16);
    CP_COMMIT();

    // x tile fp32, coalesced
    for (int i = tid; i < CHW * 128; i += 256) {
        int c = i >> 7, n = i & 127;
        xsf[c * 132 + n] = x[((size_t)b * CHW + c) * NTOK + n0 + n];
    }
    __syncthreads();

    // transpose-convert x -> bf16 [tok][c]
    {
        int n = tid >> 1, ch = (tid & 1) * 32;
        uint32_t u[16];
        #pragma unroll
        for (int j = 0; j < 16; j++)
            u[j] = pack_bf16(xsf[(ch + 2*j) * 132 + n], xsf[(ch + 2*j + 1) * 132 + n]);
        uint4* d4 = (uint4*)(psm + PXB + n * 144 + ch * 2);
        #pragma unroll
        for (int j = 0; j < 4; j++)
            d4[j] = make_uint4(u[4*j], u[4*j+1], u[4*j+2], u[4*j+3]);
    }
    CP_WAIT(0);
    __syncthreads();

    uint32_t af[4][4];
    {
        uint32_t arow = sb + PXB + (w * 16 + (lane & 15)) * 144 + (lane >> 4) * 16;
        #pragma unroll
        for (int kc = 0; kc < 4; kc++)
            ldsm_x4(af[kc], arow + kc * 32);
    }

    const float* biasf = (const float*)(psm + PBI);
    const uint32_t wrow = sb + PWB + (lane & 15) * 144 + (lane >> 4) * 16;

    #pragma unroll
    for (int m = 0; m < 3; m++) {
        float acc[4][2][4];
        #pragma unroll
        for (int i = 0; i < 4; i++)
            #pragma unroll
            for (int s2 = 0; s2 < 2; s2++)
                #pragma unroll
                for (int j = 0; j < 4; j++) acc[i][s2][j] = 0.f;

        #pragma unroll
        for (int nth = 0; nth < 4; nth++) {
            #pragma unroll
            for (int kc = 0; kc < 4; kc++) {
                uint32_t bf[4];
                ldsm_x4(bf, wrow + m * 9216 + nth * 16 * 144 + kc * 32);
                mma_bf16(acc[nth][0], af[kc], bf[0], bf[2]);
                mma_bf16(acc[nth][1], af[kc], bf[1], bf[3]);
            }
        }

        const size_t r0 = (size_t)(b * NTOK + n0 + w * 16 + g) * DDIM;
        const size_t r1 = r0 + 8 * DDIM;
        #pragma unroll
        for (int nth = 0; nth < 4; nth++) {
            #pragma unroll
            for (int s2 = 0; s2 < 2; s2++) {
                int d0 = nth * 16 + s2 * 8 + 2 * tc;
                float bb0 = biasf[m * 64 + d0], bb1 = biasf[m * 64 + d0 + 1];
                float v00 = acc[nth][s2][0] + bb0, v01 = acc[nth][s2][1] + bb1;
                float v10 = acc[nth][s2][2] + bb0, v11 = acc[nth][s2][3] + bb1;
                if (m < 2) {
                    __nv_bfloat16* dst = (m == 0) ? g_q : g_k;
                    *(uint32_t*)(dst + r0 + d0) = pack_bf16(v00, v01);
                    *(uint32_t*)(dst + r1 + d0) = pack_bf16(v10, v11);
                } else {
                    *(uint32_t*)(g_v + r0 + d0) = pack_f16(v00, v01);
                    *(uint32_t*)(g_v + r1 + d0) = pack_f16(v10, v11);
                }
            }
        }
    }
}

// ---------------------------------------------------------------------------
// Kernel 2: FA2 attention (round-5 structure) + transposed fp32 epilogue.
// grid 128, 256 threads, warp w owns q rows 16w..16w+15.
// smem: Q[128][72] + K[2][128][72] + V[2][128][72] bf16/f16 = 92160 B
// ---------------------------------------------------------------------------
#define SQ  0
#define SK  18432
#define SV  (18432 * 3)
#define SM_DYN (18432 * 5)

__device__ __forceinline__ void prefetch_kv(uint32_t sb, int b, int it, int p, int tid) {
    const uint4* ks = (const uint4*)(g_k + ((size_t)(b * NTOK + it * 128)) * DDIM);
    const uint4* vs = (const uint4*)(g_v + ((size_t)(b * NTOK + it * 128)) * DDIM);
    #pragma unroll
    for (int c = tid, j = 0; j < 4; j++, c += 256) {
        int r = c >> 3, c8 = c & 7;
        uint32_t off = r * ROWB + c8 * 16;
        cp16(sb + SK + p * 18432 + off, ks + c);
        cp16(sb + SV + p * 18432 + off, vs + c);
    }
    CP_COMMIT();
}

__global__ __launch_bounds__(256, 1) void attn_kernel()
{
    extern __shared__ char smc[];
    const uint32_t sb = smem_u32(smc);

    const int tid  = threadIdx.x;
    const int w    = tid >> 5;
    const int lane = tid & 31;
    const int g    = lane >> 2;
    const int tc   = lane & 3;
    const int b    = blockIdx.x >> 6;
    const int n0   = (blockIdx.x & 63) * 128;

    prefetch_kv(sb, b, 0, 0, tid);

    {
        const uint4* src = (const uint4*)(g_q + ((size_t)(b * NTOK + n0)) * DDIM);
        #pragma unroll
        for (int c = tid, j = 0; j < 4; j++, c += 256) {
            int r = c >> 3, c8 = c & 7;
            *(uint4*)(smc + SQ + r * ROWB + c8 * 16) = src[c];
        }
    }
    __syncthreads();

    uint32_t qa[4][4];
    {
        uint32_t rowaddr = sb + SQ + (w * 16 + (lane & 15)) * ROWB + (lane >> 4) * 16;
        #pragma unroll
        for (int kc = 0; kc < 4; kc++)
            ldsm_x4(qa[kc], rowaddr + kc * 32);
    }

    float Oc[8][4];
    #pragma unroll
    for (int i = 0; i < 8; i++)
        #pragma unroll
        for (int j = 0; j < 4; j++) Oc[i][j] = 0.f;
    float ls0 = 0.f, ls1 = 0.f;

    for (int it = 0; it < NIT; it++) {
        const int p = it & 1;
        if (it + 1 < NIT) { prefetch_kv(sb, b, it + 1, p ^ 1, tid); CP_WAIT(1); }
        else              { CP_WAIT(0); }
        __syncthreads();

        const uint32_t kb = sb + SK + p * 18432;
        const uint32_t vb = sb + SV + p * 18432;
        const uint32_t lrow = (lane & 15) * ROWB + (lane >> 4) * 16;

        // ---- S(16x128) = Q * K^T (log2-domain) ----
        float S[16][4];
        #pragma unroll
        for (int nth = 0; nth < 8; nth++) {
            #pragma unroll
            for (int j = 0; j < 4; j++) { S[2*nth][j] = 0.f; S[2*nth+1][j] = 0.f; }
            #pragma unroll
            for (int kc = 0; kc < 4; kc++) {
                uint32_t kf[4];
                ldsm_x4(kf, kb + nth * 16 * ROWB + lrow + kc * 32);
                mma_bf16(S[2*nth],     qa[kc], kf[0], kf[2]);
                mma_bf16(S[2*nth + 1], qa[kc], kf[1], kf[3]);
            }
        }

        // ---- fused exp + PV per 16-key chunk ----
        uint32_t s0a = 0u, s1a = 0u;
        #pragma unroll
        for (int kc2 = 0; kc2 < 8; kc2++) {
            uint32_t pab[4];
            pab[0] = ex2_h2(pack_f16(S[2*kc2][0],   S[2*kc2][1]));
            pab[1] = ex2_h2(pack_f16(S[2*kc2][2],   S[2*kc2][3]));
            pab[2] = ex2_h2(pack_f16(S[2*kc2+1][0], S[2*kc2+1][1]));
            pab[3] = ex2_h2(pack_f16(S[2*kc2+1][2], S[2*kc2+1][3]));
            s0a = hadd2(hadd2(s0a, pab[0]), pab[2]);
            s1a = hadd2(hadd2(s1a, pab[1]), pab[3]);
            #pragma unroll
            for (int ntp = 0; ntp < 4; ntp++) {
                uint32_t vf[4];
                ldsm_x4_t(vf, vb + kc2 * 16 * ROWB + lrow + ntp * 32);
                mma_f16(Oc[2*ntp],     pab, vf[0], vf[1]);
                mma_f16(Oc[2*ntp + 1], pab, vf[2], vf[3]);
            }
        }
        {
            float2 f0 = h2_to_f2(s0a), f1 = h2_to_f2(s1a);
            ls0 += f0.x + f0.y;
            ls1 += f1.x + f1.y;
        }
        __syncthreads();
    }

    // ---- epilogue: normalize + in-smem transpose + coalesced [b][d][n] write ----
    ls0 += __shfl_xor_sync(0xffffffffu, ls0, 1);
    ls0 += __shfl_xor_sync(0xffffffffu, ls0, 2);
    ls1 += __shfl_xor_sync(0xffffffffu, ls1, 1);
    ls1 += __shfl_xor_sync(0xffffffffu, ls1, 2);
    const float inv0 = 1.0f / ls0, inv1 = 1.0f / ls1;

    float* osm = (float*)(smc + SK);   // [64 d][132] fp32 (reuse K/V buffers; 33.8 KB)
    {
        int r0 = w * 16 + g, r1 = r0 + 8;
        #pragma unroll
        for (int nt = 0; nt < 8; nt++) {
            int d0 = nt * 8 + 2 * tc;
            osm[ d0      * 132 + r0] = Oc[nt][0] * inv0;
            osm[(d0 + 1) * 132 + r0] = Oc[nt][1] * inv0;
            osm[ d0      * 132 + r1] = Oc[nt][2] * inv1;
            osm[(d0 + 1) * 132 + r1] = Oc[nt][3] * inv1;
        }
    }
    __syncthreads();

    {
        const int n4 = (tid & 31) * 4;
        #pragma unroll
        for (int p2 = 0; p2 < 8; p2++) {
            int d = (tid >> 5) + 8 * p2;
            float4 v = *(float4*)&osm[d * 132 + n4];
            *(float4*)(g_ot + ((size_t)(b * DDIM + d)) * NTOK + n0 + n4) = v;
        }
    }
}

// ---------------------------------------------------------------------------
// Kernel 3: t-reduction, coalesced reads AND writes (g_ot is [b][d][n]).
// grid 512, 256 threads; out[b][d][yx] = sum_t g_ot[b][d][t*1024+yx]
// ---------------------------------------------------------------------------
__global__ __launch_bounds__(256) void reduce_kernel(float* __restrict__ out)
{
    int idx = blockIdx.x * 256 + threadIdx.x;     // 0 .. 131071
    int yx = idx & (HW - 1);
    int d  = (idx >> 10) & 63;
    int b  = idx >> 16;
    const float* src = g_ot + ((size_t)(b * DDIM + d)) * NTOK + yx;
    float acc = 0.f;
    #pragma unroll
    for (int t = 0; t < TDIM; t++)
        acc += src[t * HW];
    out[idx] = acc;
}

// ---------------------------------------------------------------------------
extern "C" void kernel_launch(void* const* d_in, const int* in_sizes, int n_in,
                              void* d_out, int out_size)
{
    const float* x  = (const float*)d_in[0];
    const float* wq = (const float*)d_in[1];
    const float* bq = (const float*)d_in[2];
    const float* wk = (const float*)d_in[3];
    const float* bk = (const float*)d_in[4];
    const float* wv = (const float*)d_in[5];
    const float* bv = (const float*)d_in[6];

    cudaFuncSetAttribute(proj_kernel,
                         cudaFuncAttributeMaxDynamicSharedMemorySize, PSM);
    cudaFuncSetAttribute(attn_kernel,
                         cudaFuncAttributeMaxDynamicSharedMemorySize, SM_DYN);

    setup_kernel<<<48, 256>>>(wq, bq, wk, bk, wv, bv);
    proj_kernel<<<BATCH * (NTOK / 128), 256, PSM>>>(x);
    attn_kernel<<<BATCH * (NTOK / 128), 256, SM_DYN>>>();
    reduce_kernel<<<BATCH * DDIM * HW / 256, 256>>>((float*)d_out);
}

// round 8
// speedup vs baseline: 1.6617x; 1.0742x over previous
#include <cuda_runtime.h>
#include <cuda_bf16.h>
#include <cuda_fp16.h>
#include <cstdint>

#define BATCH 2
#define CHW   64
#define DDIM  64
#define NTOK  8192
#define HW    1024
#define TDIM  8
#define NIT2  32         // key blocks per split-K CTA
#define ROWB  144        // 144 B smem row stride (72 halfwords)
#define QSCALE 0.180336880111120426f   // 0.125 * log2(e): softmax in base-2

// -------- global scratch (allocations forbidden) --------
__device__ __align__(256) __nv_bfloat16 g_q [BATCH * NTOK * DDIM];  // pre-scaled by QSCALE
__device__ __align__(256) __nv_bfloat16 g_k [BATCH * NTOK * DDIM];
__device__ __align__(256) __half        g_v [BATCH * NTOK * DDIM];
__device__ __align__(256) float         g_ot[2 * BATCH * DDIM * NTOK]; // unnorm O, [split][b][d][n]
__device__ __align__(256) float         g_l [2 * BATCH * NTOK];        // partial row sums
__device__ __align__(256) float         g_linv[BATCH * NTOK];          // 1/(l0+l1)
__device__ __align__(256) __nv_bfloat16 g_wb[3 * DDIM * CHW];          // bf16 W (wq pre-scaled)
__device__ __align__(256) float         g_bias[3 * DDIM];              // bq pre-scaled

// ---------------- helpers ----------------
__device__ __forceinline__ uint32_t smem_u32(const void* p) {
    uint32_t a;
    asm("{ .reg .u64 t; cvta.to.shared.u64 t, %1; cvt.u32.u64 %0, t; }" : "=r"(a) : "l"(p));
    return a;
}
__device__ __forceinline__ void cp16(uint32_t saddr, const void* gaddr) {
    asm volatile("cp.async.cg.shared.global [%0], [%1], 16;" :: "r"(saddr), "l"(gaddr) : "memory");
}
#define CP_COMMIT() asm volatile("cp.async.commit_group;" ::: "memory")
#define CP_WAIT(n)  asm volatile("cp.async.wait_group %0;" :: "n"(n) : "memory")

__device__ __forceinline__ void ldsm_x4(uint32_t* r, uint32_t a) {
    asm volatile("ldmatrix.sync.aligned.m8n8.x4.shared.b16 {%0,%1,%2,%3}, [%4];"
                 : "=r"(r[0]), "=r"(r[1]), "=r"(r[2]), "=r"(r[3]) : "r"(a));
}
__device__ __forceinline__ void ldsm_x4_t(uint32_t* r, uint32_t a) {
    asm volatile("ldmatrix.sync.aligned.m8n8.x4.trans.shared.b16 {%0,%1,%2,%3}, [%4];"
                 : "=r"(r[0]), "=r"(r[1]), "=r"(r[2]), "=r"(r[3]) : "r"(a));
}
__device__ __forceinline__ void mma_bf16(float* c, const uint32_t* a, uint32_t b0, uint32_t b1) {
    asm volatile(
        "mma.sync.aligned.m16n8k16.row.col.f32.bf16.bf16.f32 "
        "{%0,%1,%2,%3}, {%4,%5,%6,%7}, {%8,%9}, {%0,%1,%2,%3};"
        : "+f"(c[0]), "+f"(c[1]), "+f"(c[2]), "+f"(c[3])
        : "r"(a[0]), "r"(a[1]), "r"(a[2]), "r"(a[3]), "r"(b0), "r"(b1));
}
__device__ __forceinline__ void mma_f16(float* c, const uint32_t* a, uint32_t b0, uint32_t b1) {
    asm volatile(
        "mma.sync.aligned.m16n8k16.row.col.f32.f16.f16.f32 "
        "{%0,%1,%2,%3}, {%4,%5,%6,%7}, {%8,%9}, {%0,%1,%2,%3};"
        : "+f"(c[0]), "+f"(c[1]), "+f"(c[2]), "+f"(c[3])
        : "r"(a[0]), "r"(a[1]), "r"(a[2]), "r"(a[3]), "r"(b0), "r"(b1));
}
__device__ __forceinline__ uint32_t pack_bf16(float lo, float hi) {
    uint32_t r;
    asm("cvt.rn.bf16x2.f32 %0, %1, %2;" : "=r"(r) : "f"(hi), "f"(lo));
    return r;
}
__device__ __forceinline__ uint32_t pack_f16(float lo, float hi) {
    uint32_t r;
    asm("cvt.rn.f16x2.f32 %0, %1, %2;" : "=r"(r) : "f"(hi), "f"(lo));
    return r;
}
__device__ __forceinline__ uint32_t ex2_h2(uint32_t a) {
    uint32_t r;
    asm("ex2.approx.f16x2 %0, %1;" : "=r"(r) : "r"(a));
    return r;
}
__device__ __forceinline__ uint32_t hadd2(uint32_t a, uint32_t b) {
    uint32_t r;
    asm("add.rn.f16x2 %0, %1, %2;" : "=r"(r) : "r"(a), "r"(b));
    return r;
}
__device__ __forceinline__ float2 h2_to_f2(uint32_t h) {
    __half2 v = *(__half2*)&h;
    return make_float2(__low2float(v), __high2float(v));
}

// ---------------------------------------------------------------------------
// Kernel 0: one-time W/bias convert (wq, bq pre-scaled by QSCALE)
// ---------------------------------------------------------------------------
__global__ __launch_bounds__(256) void setup_kernel(
    const float* __restrict__ wq, const float* __restrict__ bq,
    const float* __restrict__ wk, const float* __restrict__ bk,
    const float* __restrict__ wv, const float* __restrict__ bv)
{
    int idx = blockIdx.x * 256 + threadIdx.x;
    if (idx < 3 * DDIM * CHW) {
        int m = idx >> 12, rc = idx & 4095;
        const float* W = (m == 0) ? wq : (m == 1) ? wk : wv;
        float sc = (m == 0) ? QSCALE : 1.0f;
        g_wb[idx] = __float2bfloat16_rn(W[rc] * sc);
    }
    if (idx < 3 * DDIM) {
        int m = idx >> 6;
        const float* Bp = (m == 0) ? bq : (m == 1) ? bk : bv;
        g_bias[idx] = Bp[idx & 63] * ((m == 0) ? QSCALE : 1.0f);
    }
}

// ---------------------------------------------------------------------------
// Kernel 1: QKV projection on HMMA (unchanged from round 7).
// ---------------------------------------------------------------------------
#define PXF 0
#define PXB 33792
#define PWB 52224
#define PBI 79872
#define PSM 80640

__global__ __launch_bounds__(256) void proj_kernel(const float* __restrict__ x)
{
    extern __shared__ char psm[];
    float* xsf = (float*)psm;
    const uint32_t sb = smem_u32(psm);

    const int tid  = threadIdx.x;
    const int w    = tid >> 5;
    const int lane = tid & 31;
    const int g    = lane >> 2;
    const int tc   = lane & 3;
    const int b    = blockIdx.x >> 6;
    const int n0   = (blockIdx.x & 63) * 128;

    #pragma unroll
    for (int j = 0; j < 6; j++) {
        int c = tid + j * 256;
        int rrow = c >> 3, c8 = c & 7;
        cp16(sb + PWB + rrow * 144 + c8 * 16, (const char*)g_wb + c * 16);
    }
    if (tid < 48) cp16(sb + PBI + tid * 16, (const char*)g_bias + tid * 16);
    CP_COMMIT();

    for (int i = tid; i < CHW * 128; i += 256) {
        int c = i >> 7, n = i & 127;
        xsf[c * 132 + n] = x[((size_t)b * CHW + c) * NTOK + n0 + n];
    }
    __syncthreads();

    {
        int n = tid >> 1, ch = (tid & 1) * 32;
        uint32_t u[16];
        #pragma unroll
        for (int j = 0; j < 16; j++)
            u[j] = pack_bf16(xsf[(ch + 2*j) * 132 + n], xsf[(ch + 2*j + 1) * 132 + n]);
        uint4* d4 = (uint4*)(psm + PXB + n * 144 + ch * 2);
        #pragma unroll
        for (int j = 0; j < 4; j++)
            d4[j] = make_uint4(u[4*j], u[4*j+1], u[4*j+2], u[4*j+3]);
    }
    CP_WAIT(0);
    __syncthreads();

    uint32_t af[4][4];
    {
        uint32_t arow = sb + PXB + (w * 16 + (lane & 15)) * 144 + (lane >> 4) * 16;
        #pragma unroll
        for (int kc = 0; kc < 4; kc++)
            ldsm_x4(af[kc], arow + kc * 32);
    }

    const float* biasf = (const float*)(psm + PBI);
    const uint32_t wrow = sb + PWB + (lane & 15) * 144 + (lane >> 4) * 16;

    #pragma unroll
    for (int m = 0; m < 3; m++) {
        float acc[4][2][4];
        #pragma unroll
        for (int i = 0; i < 4; i++)
            #pragma unroll
            for (int s2 = 0; s2 < 2; s2++)
                #pragma unroll
                for (int j = 0; j < 4; j++) acc[i][s2][j] = 0.f;

        #pragma unroll
        for (int nth = 0; nth < 4; nth++) {
            #pragma unroll
            for (int kc = 0; kc < 4; kc++) {
                uint32_t bf[4];
                ldsm_x4(bf, wrow + m * 9216 + nth * 16 * 144 + kc * 32);
                mma_bf16(acc[nth][0], af[kc], bf[0], bf[2]);
                mma_bf16(acc[nth][1], af[kc], bf[1], bf[3]);
            }
        }

        const size_t r0 = (size_t)(b * NTOK + n0 + w * 16 + g) * DDIM;
        const size_t r1 = r0 + 8 * DDIM;
        #pragma unroll
        for (int nth = 0; nth < 4; nth++) {
            #pragma unroll
            for (int s2 = 0; s2 < 2; s2++) {
                int d0 = nth * 16 + s2 * 8 + 2 * tc;
                float bb0 = biasf[m * 64 + d0], bb1 = biasf[m * 64 + d0 + 1];
                float v00 = acc[nth][s2][0] + bb0, v01 = acc[nth][s2][1] + bb1;
                float v10 = acc[nth][s2][2] + bb0, v11 = acc[nth][s2][3] + bb1;
                if (m < 2) {
                    __nv_bfloat16* dst = (m == 0) ? g_q : g_k;
                    *(uint32_t*)(dst + r0 + d0) = pack_bf16(v00, v01);
                    *(uint32_t*)(dst + r1 + d0) = pack_bf16(v10, v11);
                } else {
                    *(uint32_t*)(g_v + r0 + d0) = pack_f16(v00, v01);
                    *(uint32_t*)(g_v + r1 + d0) = pack_f16(v10, v11);
                }
            }
        }
    }
}

// ---------------------------------------------------------------------------
// Kernel 2: split-K FA2 attention. grid 256 = b x 64 q-tiles x 2 key halves.
// 256 threads, 2 CTAs/SM co-resident (regs<=128 via half-S tiles).
// Partials are additive (no-max softmax): O_total = O0+O1, l_total = l0+l1.
// ---------------------------------------------------------------------------
#define SQ  0
#define SK  18432
#define SV  (18432 * 3)
#define SM_DYN (18432 * 5)

__device__ __forceinline__ void prefetch_kv(uint32_t sb, size_t kbase, int p, int tid) {
    const uint4* ks = (const uint4*)(g_k + kbase * DDIM);
    const uint4* vs = (const uint4*)(g_v + kbase * DDIM);
    #pragma unroll
    for (int c = tid, j = 0; j < 4; j++, c += 256) {
        int r = c >> 3, c8 = c & 7;
        uint32_t off = r * ROWB + c8 * 16;
        cp16(sb + SK + p * 18432 + off, ks + c);
        cp16(sb + SV + p * 18432 + off, vs + c);
    }
    CP_COMMIT();
}

__global__ __launch_bounds__(256, 2) void attn_kernel()
{
    extern __shared__ char smc[];
    const uint32_t sb = smem_u32(smc);

    const int tid   = threadIdx.x;
    const int w     = tid >> 5;
    const int lane  = tid & 31;
    const int g     = lane >> 2;
    const int tc    = lane & 3;
    const int b     = blockIdx.x >> 7;
    const int n0    = ((blockIdx.x >> 1) & 63) * 128;
    const int split = blockIdx.x & 1;
    const size_t kstart = (size_t)b * NTOK + split * (NTOK / 2);

    prefetch_kv(sb, kstart, 0, tid);

    {
        const uint4* src = (const uint4*)(g_q + ((size_t)(b * NTOK + n0)) * DDIM);
        #pragma unroll
        for (int c = tid, j = 0; j < 4; j++, c += 256) {
            int r = c >> 3, c8 = c & 7;
            *(uint4*)(smc + SQ + r * ROWB + c8 * 16) = src[c];
        }
    }
    __syncthreads();

    uint32_t qa[4][4];
    {
        uint32_t rowaddr = sb + SQ + (w * 16 + (lane & 15)) * ROWB + (lane >> 4) * 16;
        #pragma unroll
        for (int kc = 0; kc < 4; kc++)
            ldsm_x4(qa[kc], rowaddr + kc * 32);
    }

    float Oc[8][4];
    #pragma unroll
    for (int i = 0; i < 8; i++)
        #pragma unroll
        for (int j = 0; j < 4; j++) Oc[i][j] = 0.f;
    float ls0 = 0.f, ls1 = 0.f;

    for (int it = 0; it < NIT2; it++) {
        const int p = it & 1;
        if (it + 1 < NIT2) { prefetch_kv(sb, kstart + (it + 1) * 128, p ^ 1, tid); CP_WAIT(1); }
        else               { CP_WAIT(0); }
        __syncthreads();

        const uint32_t kb = sb + SK + p * 18432;
        const uint32_t vb = sb + SV + p * 18432;
        const uint32_t lrow = (lane & 15) * ROWB + (lane >> 4) * 16;

        uint32_t s0a = 0u, s1a = 0u;
        #pragma unroll
        for (int h = 0; h < 2; h++) {                 // 64-key half-tiles
            float S[8][4];
            #pragma unroll
            for (int nth = 0; nth < 4; nth++) {
                #pragma unroll
                for (int j = 0; j < 4; j++) { S[2*nth][j] = 0.f; S[2*nth+1][j] = 0.f; }
                #pragma unroll
                for (int kc = 0; kc < 4; kc++) {
                    uint32_t kf[4];
                    ldsm_x4(kf, kb + (h * 4 + nth) * 16 * ROWB + lrow + kc * 32);
                    mma_bf16(S[2*nth],     qa[kc], kf[0], kf[2]);
                    mma_bf16(S[2*nth + 1], qa[kc], kf[1], kf[3]);
                }
            }
            #pragma unroll
            for (int kc2 = 0; kc2 < 4; kc2++) {
                uint32_t pab[4];
                pab[0] = ex2_h2(pack_f16(S[2*kc2][0],   S[2*kc2][1]));
                pab[1] = ex2_h2(pack_f16(S[2*kc2][2],   S[2*kc2][3]));
                pab[2] = ex2_h2(pack_f16(S[2*kc2+1][0], S[2*kc2+1][1]));
                pab[3] = ex2_h2(pack_f16(S[2*kc2+1][2], S[2*kc2+1][3]));
                s0a = hadd2(hadd2(s0a, pab[0]), pab[2]);
                s1a = hadd2(hadd2(s1a, pab[1]), pab[3]);
                #pragma unroll
                for (int ntp = 0; ntp < 4; ntp++) {
                    uint32_t vf[4];
                    ldsm_x4_t(vf, vb + (h * 4 + kc2) * 16 * ROWB + lrow + ntp * 32);
                    mma_f16(Oc[2*ntp],     pab, vf[0], vf[1]);
                    mma_f16(Oc[2*ntp + 1], pab, vf[2], vf[3]);
                }
            }
        }
        {
            float2 f0 = h2_to_f2(s0a), f1 = h2_to_f2(s1a);
            ls0 += f0.x + f0.y;
            ls1 += f1.x + f1.y;
        }
        __syncthreads();
    }

    // ---- epilogue: reduce l, store UNNORMALIZED O transposed + l partials ----
    ls0 += __shfl_xor_sync(0xffffffffu, ls0, 1);
    ls0 += __shfl_xor_sync(0xffffffffu, ls0, 2);
    ls1 += __shfl_xor_sync(0xffffffffu, ls1, 1);
    ls1 += __shfl_xor_sync(0xffffffffu, ls1, 2);
    if (tc == 0) {
        float* lp = g_l + (size_t)split * (BATCH * NTOK) + (size_t)b * NTOK + n0 + w * 16 + g;
        lp[0] = ls0;
        lp[8] = ls1;
    }

    float* osm = (float*)(smc + SK);   // [64 d][132] fp32 (reuse K/V buffers)
    {
        int r0 = w * 16 + g, r1 = r0 + 8;
        #pragma unroll
        for (int nt = 0; nt < 8; nt++) {
            int d0 = nt * 8 + 2 * tc;
            osm[ d0      * 132 + r0] = Oc[nt][0];
            osm[(d0 + 1) * 132 + r0] = Oc[nt][1];
            osm[ d0      * 132 + r1] = Oc[nt][2];
            osm[(d0 + 1) * 132 + r1] = Oc[nt][3];
        }
    }
    __syncthreads();

    {
        const int n4 = (tid & 31) * 4;
        float* dstb = g_ot + (size_t)split * (BATCH * DDIM * NTOK);
        #pragma unroll
        for (int p2 = 0; p2 < 8; p2++) {
            int d = (tid >> 5) + 8 * p2;
            float4 v = *(float4*)&osm[d * 132 + n4];
            *(float4*)(dstb + ((size_t)(b * DDIM + d)) * NTOK + n0 + n4) = v;
        }
    }
}

// ---------------------------------------------------------------------------
// Kernel 2b: combine split-K row sums -> 1/(l0+l1)
// ---------------------------------------------------------------------------
__global__ __launch_bounds__(256) void lnorm_kernel()
{
    int i = blockIdx.x * 256 + threadIdx.x;   // BATCH*NTOK = 16384
    g_linv[i] = 1.0f / (g_l[i] + g_l[BATCH * NTOK + i]);
}

// ---------------------------------------------------------------------------
// Kernel 3: t-reduction, combines split-K partials and normalizes.
// ---------------------------------------------------------------------------
__global__ __launch_bounds__(256) void reduce_kernel(float* __restrict__ out)
{
    int idx = blockIdx.x * 256 + threadIdx.x;     // 0 .. 131071
    int yx = idx & (HW - 1);
    int d  = (idx >> 10) & 63;
    int b  = idx >> 16;
    const float* s0 = g_ot + ((size_t)(b * DDIM + d)) * NTOK + yx;
    const float* s1 = s0 + (size_t)BATCH * DDIM * NTOK;
    const float* li = g_linv + (size_t)b * NTOK + yx;
    float acc = 0.f;
    #pragma unroll
    for (int t = 0; t < TDIM; t++)
        acc += (s0[t * HW] + s1[t * HW]) * li[t * HW];
    out[idx] = acc;
}

// ---------------------------------------------------------------------------
extern "C" void kernel_launch(void* const* d_in, const int* in_sizes, int n_in,
                              void* d_out, int out_size)
{
    const float* x  = (const float*)d_in[0];
    const float* wq = (const float*)d_in[1];
    const float* bq = (const float*)d_in[2];
    const float* wk = (const float*)d_in[3];
    const float* bk = (const float*)d_in[4];
    const float* wv = (const float*)d_in[5];
    const float* bv = (const float*)d_in[6];

    cudaFuncSetAttribute(proj_kernel,
                         cudaFuncAttributeMaxDynamicSharedMemorySize, PSM);
    cudaFuncSetAttribute(attn_kernel,
                         cudaFuncAttributeMaxDynamicSharedMemorySize, SM_DYN);

    setup_kernel<<<48, 256>>>(wq, bq, wk, bk, wv, bv);
    proj_kernel<<<BATCH * (NTOK / 128), 256, PSM>>>(x);
    attn_kernel<<<BATCH * (NTOK / 128) * 2, 256, SM_DYN>>>();
    lnorm_kernel<<<BATCH * NTOK / 256, 256>>>();
    reduce_kernel<<<BATCH * DDIM * HW / 256, 256>>>((float*)d_out);
}

// round 9
// speedup vs baseline: 1.8753x; 1.1286x over previous
#include <cuda_runtime.h>
#include <cuda_bf16.h>
#include <cuda_fp16.h>
#include <cstdint>

#define BATCH 2
#define CHW   64
#define DDIM  64
#define NTOK  8192
#define HW    1024
#define TDIM  8
#define NCTA  296        // 2 x 148 SMs, balanced persistent schedule
#define NITEMS 8192      // 128 q-tiles x 64 key blocks
#define NSLOT 4
#define ROWB  144        // 144 B smem row stride (72 halfwords)
#define QSCALE 0.180336880111120426f   // 0.125 * log2(e): softmax in base-2

// -------- global scratch (allocations forbidden) --------
__device__ __align__(256) __nv_bfloat16 g_q [BATCH * NTOK * DDIM];  // pre-scaled by QSCALE
__device__ __align__(256) __nv_bfloat16 g_k [BATCH * NTOK * DDIM];
__device__ __align__(256) __half        g_v [BATCH * NTOK * DDIM];
__device__ __align__(256) float g_ot[NSLOT * BATCH * DDIM * NTOK];  // unnorm O partials [slot][b][d][n]
__device__ __align__(256) float g_l [NSLOT * BATCH * NTOK];         // l partials [slot][b][n]
__device__ __align__(256) __nv_bfloat16 g_wb[3 * DDIM * CHW];       // bf16 W (wq pre-scaled)
__device__ __align__(256) float         g_bias[3 * DDIM];           // bq pre-scaled

// ---------------- helpers ----------------
__device__ __forceinline__ uint32_t smem_u32(const void* p) {
    uint32_t a;
    asm("{ .reg .u64 t; cvta.to.shared.u64 t, %1; cvt.u32.u64 %0, t; }" : "=r"(a) : "l"(p));
    return a;
}
__device__ __forceinline__ void cp16(uint32_t saddr, const void* gaddr) {
    asm volatile("cp.async.cg.shared.global [%0], [%1], 16;" :: "r"(saddr), "l"(gaddr) : "memory");
}
#define CP_COMMIT() asm volatile("cp.async.commit_group;" ::: "memory")
#define CP_WAIT(n)  asm volatile("cp.async.wait_group %0;" :: "n"(n) : "memory")

__device__ __forceinline__ void ldsm_x4(uint32_t* r, uint32_t a) {
    asm volatile("ldmatrix.sync.aligned.m8n8.x4.shared.b16 {%0,%1,%2,%3}, [%4];"
                 : "=r"(r[0]), "=r"(r[1]), "=r"(r[2]), "=r"(r[3]) : "r"(a));
}
__device__ __forceinline__ void ldsm_x4_t(uint32_t* r, uint32_t a) {
    asm volatile("ldmatrix.sync.aligned.m8n8.x4.trans.shared.b16 {%0,%1,%2,%3}, [%4];"
                 : "=r"(r[0]), "=r"(r[1]), "=r"(r[2]), "=r"(r[3]) : "r"(a));
}
__device__ __forceinline__ void mma_bf16(float* c, const uint32_t* a, uint32_t b0, uint32_t b1) {
    asm volatile(
        "mma.sync.aligned.m16n8k16.row.col.f32.bf16.bf16.f32 "
        "{%0,%1,%2,%3}, {%4,%5,%6,%7}, {%8,%9}, {%0,%1,%2,%3};"
        : "+f"(c[0]), "+f"(c[1]), "+f"(c[2]), "+f"(c[3])
        : "r"(a[0]), "r"(a[1]), "r"(a[2]), "r"(a[3]), "r"(b0), "r"(b1));
}
__device__ __forceinline__ void mma_f16(float* c, const uint32_t* a, uint32_t b0, uint32_t b1) {
    asm volatile(
        "mma.sync.aligned.m16n8k16.row.col.f32.f16.f16.f32 "
        "{%0,%1,%2,%3}, {%4,%5,%6,%7}, {%8,%9}, {%0,%1,%2,%3};"
        : "+f"(c[0]), "+f"(c[1]), "+f"(c[2]), "+f"(c[3])
        : "r"(a[0]), "r"(a[1]), "r"(a[2]), "r"(a[3]), "r"(b0), "r"(b1));
}
__device__ __forceinline__ uint32_t pack_bf16(float lo, float hi) {
    uint32_t r;
    asm("cvt.rn.bf16x2.f32 %0, %1, %2;" : "=r"(r) : "f"(hi), "f"(lo));
    return r;
}
__device__ __forceinline__ uint32_t pack_f16(float lo, float hi) {
    uint32_t r;
    asm("cvt.rn.f16x2.f32 %0, %1, %2;" : "=r"(r) : "f"(hi), "f"(lo));
    return r;
}
__device__ __forceinline__ uint32_t ex2_h2(uint32_t a) {
    uint32_t r;
    asm("ex2.approx.f16x2 %0, %1;" : "=r"(r) : "r"(a));
    return r;
}
__device__ __forceinline__ uint32_t hadd2(uint32_t a, uint32_t b) {
    uint32_t r;
    asm("add.rn.f16x2 %0, %1, %2;" : "=r"(r) : "r"(a), "r"(b));
    return r;
}
__device__ __forceinline__ float2 h2_to_f2(uint32_t h) {
    __half2 v = *(__half2*)&h;
    return make_float2(__low2float(v), __high2float(v));
}

// ---------------------------------------------------------------------------
// Kernel 0: one-time W/bias convert (wq, bq pre-scaled by QSCALE)
// ---------------------------------------------------------------------------
__global__ __launch_bounds__(256) void setup_kernel(
    const float* __restrict__ wq, const float* __restrict__ bq,
    const float* __restrict__ wk, const float* __restrict__ bk,
    const float* __restrict__ wv, const float* __restrict__ bv)
{
    int idx = blockIdx.x * 256 + threadIdx.x;
    if (idx < 3 * DDIM * CHW) {
        int m = idx >> 12, rc = idx & 4095;
        const float* W = (m == 0) ? wq : (m == 1) ? wk : wv;
        float sc = (m == 0) ? QSCALE : 1.0f;
        g_wb[idx] = __float2bfloat16_rn(W[rc] * sc);
    }
    if (idx < 3 * DDIM) {
        int m = idx >> 6;
        const float* Bp = (m == 0) ? bq : (m == 1) ? bk : bv;
        g_bias[idx] = Bp[idx & 63] * ((m == 0) ? QSCALE : 1.0f);
    }
}

// ---------------------------------------------------------------------------
// Kernel 1: QKV projection on HMMA (unchanged).
// ---------------------------------------------------------------------------
#define PXF 0
#define PXB 33792
#define PWB 52224
#define PBI 79872
#define PSM 80640

__global__ __launch_bounds__(256) void proj_kernel(const float* __restrict__ x)
{
    extern __shared__ char psm[];
    float* xsf = (float*)psm;
    const uint32_t sb = smem_u32(psm);

    const int tid  = threadIdx.x;
    const int w    = tid >> 5;
    const int lane = tid & 31;
    const int g    = lane >> 2;
    const int tc   = lane & 3;
    const int b    = blockIdx.x >> 6;
    const int n0   = (blockIdx.x & 63) * 128;

    #pragma unroll
    for (int j = 0; j < 6; j++) {
        int c = tid + j * 256;
        int rrow = c >> 3, c8 = c & 7;
        cp16(sb + PWB + rrow * 144 + c8 * 16, (const char*)g_wb + c * 16);
    }
    if (tid < 48) cp16(sb + PBI + tid * 16, (const char*)g_bias + tid * 16);
    CP_COMMIT();

    for (int i = tid; i < CHW * 128; i += 256) {
        int c = i >> 7, n = i & 127;
        xsf[c * 132 + n] = x[((size_t)b * CHW + c) * NTOK + n0 + n];
    }
    __syncthreads();

    {
        int n = tid >> 1, ch = (tid & 1) * 32;
        uint32_t u[16];
        #pragma unroll
        for (int j = 0; j < 16; j++)
            u[j] = pack_bf16(xsf[(ch + 2*j) * 132 + n], xsf[(ch + 2*j + 1) * 132 + n]);
        uint4* d4 = (uint4*)(psm + PXB + n * 144 + ch * 2);
        #pragma unroll
        for (int j = 0; j < 4; j++)
            d4[j] = make_uint4(u[4*j], u[4*j+1], u[4*j+2], u[4*j+3]);
    }
    CP_WAIT(0);
    __syncthreads();

    uint32_t af[4][4];
    {
        uint32_t arow = sb + PXB + (w * 16 + (lane & 15)) * 144 + (lane >> 4) * 16;
        #pragma unroll
        for (int kc = 0; kc < 4; kc++)
            ldsm_x4(af[kc], arow + kc * 32);
    }

    const float* biasf = (const float*)(psm + PBI);
    const uint32_t wrow = sb + PWB + (lane & 15) * 144 + (lane >> 4) * 16;

    #pragma unroll
    for (int m = 0; m < 3; m++) {
        float acc[4][2][4];
        #pragma unroll
        for (int i = 0; i < 4; i++)
            #pragma unroll
            for (int s2 = 0; s2 < 2; s2++)
                #pragma unroll
                for (int j = 0; j < 4; j++) acc[i][s2][j] = 0.f;

        #pragma unroll
        for (int nth = 0; nth < 4; nth++) {
            #pragma unroll
            for (int kc = 0; kc < 4; kc++) {
                uint32_t bf[4];
                ldsm_x4(bf, wrow + m * 9216 + nth * 16 * 144 + kc * 32);
                mma_bf16(acc[nth][0], af[kc], bf[0], bf[2]);
                mma_bf16(acc[nth][1], af[kc], bf[1], bf[3]);
            }
        }

        const size_t r0 = (size_t)(b * NTOK + n0 + w * 16 + g) * DDIM;
        const size_t r1 = r0 + 8 * DDIM;
        #pragma unroll
        for (int nth = 0; nth < 4; nth++) {
            #pragma unroll
            for (int s2 = 0; s2 < 2; s2++) {
                int d0 = nth * 16 + s2 * 8 + 2 * tc;
                float bb0 = biasf[m * 64 + d0], bb1 = biasf[m * 64 + d0 + 1];
                float v00 = acc[nth][s2][0] + bb0, v01 = acc[nth][s2][1] + bb1;
                float v10 = acc[nth][s2][2] + bb0, v11 = acc[nth][s2][3] + bb1;
                if (m < 2) {
                    __nv_bfloat16* dst = (m == 0) ? g_q : g_k;
                    *(uint32_t*)(dst + r0 + d0) = pack_bf16(v00, v01);
                    *(uint32_t*)(dst + r1 + d0) = pack_bf16(v10, v11);
                } else {
                    *(uint32_t*)(g_v + r0 + d0) = pack_f16(v00, v01);
                    *(uint32_t*)(g_v + r1 + d0) = pack_f16(v10, v11);
                }
            }
        }
    }
}

// ---------------------------------------------------------------------------
// Kernel 2: balanced persistent FA2 attention.
// grid 296 (= 2 CTAs/SM via bid%148 placement), 256 threads, 2 CTAs/SM.
// Flattened item list: item = qtile*64 + kblock; CTA bid handles
// [bid*8192/296, (bid+1)*8192/296) -> 27-28 items, <=2 q-tiles.
// Per q-tile <=4 contributing CTAs; partial slot = bid - firstCTA(tile).
// ---------------------------------------------------------------------------
#define SQ  0
#define SK  18432
#define SV  (18432 * 3)
#define SM_DYN (18432 * 5)

__device__ __forceinline__ void prefetch_kv(uint32_t sb, int item, int tid) {
    const int q  = item >> 6;
    const size_t kbase = (size_t)(q >> 6) * NTOK + (item & 63) * 128;
    const int p  = item & 1;
    const uint4* ks = (const uint4*)(g_k + kbase * DDIM);
    const uint4* vs = (const uint4*)(g_v + kbase * DDIM);
    #pragma unroll
    for (int c = tid, j = 0; j < 4; j++, c += 256) {
        int r = c >> 3, c8 = c & 7;
        uint32_t off = r * ROWB + c8 * 16;
        cp16(sb + SK + p * 18432 + off, ks + c);
        cp16(sb + SV + p * 18432 + off, vs + c);
    }
    CP_COMMIT();
}

__global__ __launch_bounds__(256, 2) void attn_kernel()
{
    extern __shared__ char smc[];
    const uint32_t sb = smem_u32(smc);

    const int bid  = blockIdx.x;
    const int tid  = threadIdx.x;
    const int w    = tid >> 5;
    const int lane = tid & 31;
    const int g    = lane >> 2;
    const int tc   = lane & 3;

    const int lo = (bid * NITEMS) / NCTA;
    const int hi = ((bid + 1) * NITEMS) / NCTA;

    prefetch_kv(sb, lo, tid);

    uint32_t qa[4][4];
    float Oc[8][4];
    float ls0, ls1;
    int qt = lo >> 6;

    // --- load Q for first tile ---
    {
        int b = qt >> 6, n0 = (qt & 63) * 128;
        const uint4* src = (const uint4*)(g_q + ((size_t)(b * NTOK + n0)) * DDIM);
        #pragma unroll
        for (int c = tid, j = 0; j < 4; j++, c += 256) {
            int r = c >> 3, c8 = c & 7;
            *(uint4*)(smc + SQ + r * ROWB + c8 * 16) = src[c];
        }
    }
    __syncthreads();
    {
        uint32_t rowaddr = sb + SQ + (w * 16 + (lane & 15)) * ROWB + (lane >> 4) * 16;
        #pragma unroll
        for (int kc = 0; kc < 4; kc++) ldsm_x4(qa[kc], rowaddr + kc * 32);
    }
    #pragma unroll
    for (int i = 0; i < 8; i++)
        #pragma unroll
        for (int j = 0; j < 4; j++) Oc[i][j] = 0.f;
    ls0 = ls1 = 0.f;

    for (int item = lo; item < hi; item++) {
        CP_WAIT(0);
        __syncthreads();
        if (item + 1 < hi) prefetch_kv(sb, item + 1, tid);

        const int q = item >> 6;
        if (q != qt) {
            // ---- flush partial for tile qt ----
            float a0 = ls0, a1 = ls1;
            a0 += __shfl_xor_sync(0xffffffffu, a0, 1);
            a0 += __shfl_xor_sync(0xffffffffu, a0, 2);
            a1 += __shfl_xor_sync(0xffffffffu, a1, 1);
            a1 += __shfl_xor_sync(0xffffffffu, a1, 2);
            int fb = qt >> 6, fn0 = (qt & 63) * 128;
            int c0 = (NCTA * (64 * qt + 1) - 1) >> 13;
            int slot = bid - c0;
            if (tc == 0) {
                float* lp = g_l + ((size_t)slot * BATCH + fb) * NTOK + fn0 + w * 16 + g;
                lp[0] = a0;
                lp[8] = a1;
            }
            {
                size_t obase = ((size_t)slot * BATCH + fb) * DDIM;
                int r0 = fn0 + w * 16 + g;
                #pragma unroll
                for (int nt = 0; nt < 8; nt++) {
                    int d0 = nt * 8 + 2 * tc;
                    g_ot[(obase + d0    ) * NTOK + r0    ] = Oc[nt][0];
                    g_ot[(obase + d0 + 1) * NTOK + r0    ] = Oc[nt][1];
                    g_ot[(obase + d0    ) * NTOK + r0 + 8] = Oc[nt][2];
                    g_ot[(obase + d0 + 1) * NTOK + r0 + 8] = Oc[nt][3];
                }
            }
            // ---- reload Q for tile q, reset accumulators ----
            {
                int b = q >> 6, n0 = (q & 63) * 128;
                const uint4* src = (const uint4*)(g_q + ((size_t)(b * NTOK + n0)) * DDIM);
                #pragma unroll
                for (int c = tid, j = 0; j < 4; j++, c += 256) {
                    int r = c >> 3, c8 = c & 7;
                    *(uint4*)(smc + SQ + r * ROWB + c8 * 16) = src[c];
                }
            }
            __syncthreads();
            {
                uint32_t rowaddr = sb + SQ + (w * 16 + (lane & 15)) * ROWB + (lane >> 4) * 16;
                #pragma unroll
                for (int kc = 0; kc < 4; kc++) ldsm_x4(qa[kc], rowaddr + kc * 32);
            }
            #pragma unroll
            for (int i = 0; i < 8; i++)
                #pragma unroll
                for (int j = 0; j < 4; j++) Oc[i][j] = 0.f;
            ls0 = ls1 = 0.f;
            qt = q;
        }

        const int p = item & 1;
        const uint32_t kb = sb + SK + p * 18432;
        const uint32_t vb = sb + SV + p * 18432;
        const uint32_t lrow = (lane & 15) * ROWB + (lane >> 4) * 16;

        uint32_t s0a = 0u, s1a = 0u;
        #pragma unroll
        for (int h = 0; h < 2; h++) {                 // 64-key half-tiles
            float S[8][4];
            #pragma unroll
            for (int nth = 0; nth < 4; nth++) {
                #pragma unroll
                for (int j = 0; j < 4; j++) { S[2*nth][j] = 0.f; S[2*nth+1][j] = 0.f; }
                #pragma unroll
                for (int kc = 0; kc < 4; kc++) {
                    uint32_t kf[4];
                    ldsm_x4(kf, kb + (h * 4 + nth) * 16 * ROWB + lrow + kc * 32);
                    mma_bf16(S[2*nth],     qa[kc], kf[0], kf[2]);
                    mma_bf16(S[2*nth + 1], qa[kc], kf[1], kf[3]);
                }
            }
            #pragma unroll
            for (int kc2 = 0; kc2 < 4; kc2++) {
                uint32_t pab[4];
                pab[0] = ex2_h2(pack_f16(S[2*kc2][0],   S[2*kc2][1]));
                pab[1] = ex2_h2(pack_f16(S[2*kc2][2],   S[2*kc2][3]));
                pab[2] = ex2_h2(pack_f16(S[2*kc2+1][0], S[2*kc2+1][1]));
                pab[3] = ex2_h2(pack_f16(S[2*kc2+1][2], S[2*kc2+1][3]));
                s0a = hadd2(hadd2(s0a, pab[0]), pab[2]);
                s1a = hadd2(hadd2(s1a, pab[1]), pab[3]);
                #pragma unroll
                for (int ntp = 0; ntp < 4; ntp++) {
                    uint32_t vf[4];
                    ldsm_x4_t(vf, vb + (h * 4 + kc2) * 16 * ROWB + lrow + ntp * 32);
                    mma_f16(Oc[2*ntp],     pab, vf[0], vf[1]);
                    mma_f16(Oc[2*ntp + 1], pab, vf[2], vf[3]);
                }
            }
        }
        {
            float2 f0 = h2_to_f2(s0a), f1 = h2_to_f2(s1a);
            ls0 += f0.x + f0.y;
            ls1 += f1.x + f1.y;
        }
    }

    // ---- final flush for last tile ----
    {
        float a0 = ls0, a1 = ls1;
        a0 += __shfl_xor_sync(0xffffffffu, a0, 1);
        a0 += __shfl_xor_sync(0xffffffffu, a0, 2);
        a1 += __shfl_xor_sync(0xffffffffu, a1, 1);
        a1 += __shfl_xor_sync(0xffffffffu, a1, 2);
        int fb = qt >> 6, fn0 = (qt & 63) * 128;
        int c0 = (NCTA * (64 * qt + 1) - 1) >> 13;
        int slot = bid - c0;
        if (tc == 0) {
            float* lp = g_l + ((size_t)slot * BATCH + fb) * NTOK + fn0 + w * 16 + g;
            lp[0] = a0;
            lp[8] = a1;
        }
        size_t obase = ((size_t)slot * BATCH + fb) * DDIM;
        int r0 = fn0 + w * 16 + g;
        #pragma unroll
        for (int nt = 0; nt < 8; nt++) {
            int d0 = nt * 8 + 2 * tc;
            g_ot[(obase + d0    ) * NTOK + r0    ] = Oc[nt][0];
            g_ot[(obase + d0 + 1) * NTOK + r0    ] = Oc[nt][1];
            g_ot[(obase + d0    ) * NTOK + r0 + 8] = Oc[nt][2];
            g_ot[(obase + d0 + 1) * NTOK + r0 + 8] = Oc[nt][3];
        }
    }
}

// ---------------------------------------------------------------------------
// Kernel 3: combine slots + normalize + t-reduce (coalesced both sides).
// ---------------------------------------------------------------------------
__global__ __launch_bounds__(256) void reduce_kernel(float* __restrict__ out)
{
    int idx = blockIdx.x * 256 + threadIdx.x;     // 0 .. 131071
    int yx = idx & (HW - 1);
    int d  = (idx >> 10) & 63;
    int b  = idx >> 16;
    const size_t SLOT_O = (size_t)BATCH * DDIM * NTOK;
    const size_t SLOT_L = (size_t)BATCH * NTOK;
    const float* o0 = g_ot + ((size_t)b * DDIM + d) * NTOK + yx;
    const float* l0 = g_l  + (size_t)b * NTOK + yx;
    float acc = 0.f;
    #pragma unroll
    for (int t = 0; t < TDIM; t++) {
        int n = t * HW;
        float ov = o0[n] + o0[SLOT_O + n] + o0[2 * SLOT_O + n] + o0[3 * SLOT_O + n];
        float lv = l0[n] + l0[SLOT_L + n] + l0[2 * SLOT_L + n] + l0[3 * SLOT_L + n];
        acc += ov * (1.0f / lv);
    }
    out[idx] = acc;
}

// ---------------------------------------------------------------------------
extern "C" void kernel_launch(void* const* d_in, const int* in_sizes, int n_in,
                              void* d_out, int out_size)
{
    const float* x  = (const float*)d_in[0];
    const float* wq = (const float*)d_in[1];
    const float* bq = (const float*)d_in[2];
    const float* wk = (const float*)d_in[3];
    const float* bk = (const float*)d_in[4];
    const float* wv = (const float*)d_in[5];
    const float* bv = (const float*)d_in[6];

    cudaFuncSetAttribute(proj_kernel,
                         cudaFuncAttributeMaxDynamicSharedMemorySize, PSM);
    cudaFuncSetAttribute(attn_kernel,
                         cudaFuncAttributeMaxDynamicSharedMemorySize, SM_DYN);

    setup_kernel<<<48, 256>>>(wq, bq, wk, bk, wv, bv);
    proj_kernel<<<BATCH * (NTOK / 128), 256, PSM>>>(x);
    attn_kernel<<<NCTA, 256, SM_DYN>>>();
    reduce_kernel<<<BATCH * DDIM * HW / 256, 256>>>((float*)d_out);
}

// round 11
// speedup vs baseline: 1.8852x; 1.0053x over previous
#include <cuda_runtime.h>
#include <cuda_bf16.h>
#include <cuda_fp16.h>
#include <cstdint>

#define BATCH 2
#define CHW   64
#define DDIM  64
#define NTOK  8192
#define HW    1024
#define TDIM  8
#define NCTA  296        // 2 x 148 SMs, balanced persistent schedule
#define NITEMS 8192      // 128 q-tiles x 64 key blocks
#define NSLOT 4
#define ROWB  144        // 144 B smem row stride (72 halfwords)
#define QSCALE 0.180336880111120426f   // 0.125 * log2(e): softmax in base-2

// -------- global scratch (allocations forbidden) --------
__device__ __align__(256) __nv_bfloat16 g_q [BATCH * NTOK * DDIM];  // pre-scaled by QSCALE
__device__ __align__(256) __nv_bfloat16 g_k [BATCH * NTOK * DDIM];
__device__ __align__(256) __half        g_v [BATCH * NTOK * DDIM];
__device__ __align__(256) __half g_oth[NSLOT * BATCH * DDIM * NTOK]; // unnorm O partials f16 [slot][b][d][n]
__device__ __align__(256) float  g_l [NSLOT * BATCH * NTOK];         // l partials [slot][b][n]
__device__ __align__(256) __nv_bfloat16 g_wb[3 * DDIM * CHW];        // bf16 W (wq pre-scaled)
__device__ __align__(256) float         g_bias[3 * DDIM];            // bq pre-scaled

// ---------------- helpers ----------------
__device__ __forceinline__ uint32_t smem_u32(const void* p) {
    uint32_t a;
    asm("{ .reg .u64 t; cvta.to.shared.u64 t, %1; cvt.u32.u64 %0, t; }" : "=r"(a) : "l"(p));
    return a;
}
__device__ __forceinline__ void cp16(uint32_t saddr, const void* gaddr) {
    asm volatile("cp.async.cg.shared.global [%0], [%1], 16;" :: "r"(saddr), "l"(gaddr) : "memory");
}
#define CP_COMMIT() asm volatile("cp.async.commit_group;" ::: "memory")
#define CP_WAIT(n)  asm volatile("cp.async.wait_group %0;" :: "n"(n) : "memory")

__device__ __forceinline__ void ldsm_x4(uint32_t* r, uint32_t a) {
    asm volatile("ldmatrix.sync.aligned.m8n8.x4.shared.b16 {%0,%1,%2,%3}, [%4];"
                 : "=r"(r[0]), "=r"(r[1]), "=r"(r[2]), "=r"(r[3]) : "r"(a));
}
__device__ __forceinline__ void ldsm_x4_t(uint32_t* r, uint32_t a) {
    asm volatile("ldmatrix.sync.aligned.m8n8.x4.trans.shared.b16 {%0,%1,%2,%3}, [%4];"
                 : "=r"(r[0]), "=r"(r[1]), "=r"(r[2]), "=r"(r[3]) : "r"(a));
}
__device__ __forceinline__ void mma_bf16(float* c, const uint32_t* a, uint32_t b0, uint32_t b1) {
    asm volatile(
        "mma.sync.aligned.m16n8k16.row.col.f32.bf16.bf16.f32 "
        "{%0,%1,%2,%3}, {%4,%5,%6,%7}, {%8,%9}, {%0,%1,%2,%3};"
        : "+f"(c[0]), "+f"(c[1]), "+f"(c[2]), "+f"(c[3])
        : "r"(a[0]), "r"(a[1]), "r"(a[2]), "r"(a[3]), "r"(b0), "r"(b1));
}
__device__ __forceinline__ void mma_f16(float* c, const uint32_t* a, uint32_t b0, uint32_t b1) {
    asm volatile(
        "mma.sync.aligned.m16n8k16.row.col.f32.f16.f16.f32 "
        "{%0,%1,%2,%3}, {%4,%5,%6,%7}, {%8,%9}, {%0,%1,%2,%3};"
        : "+f"(c[0]), "+f"(c[1]), "+f"(c[2]), "+f"(c[3])
        : "r"(a[0]), "r"(a[1]), "r"(a[2]), "r"(a[3]), "r"(b0), "r"(b1));
}
__device__ __forceinline__ uint32_t pack_bf16(float lo, float hi) {
    uint32_t r;
    asm("cvt.rn.bf16x2.f32 %0, %1, %2;" : "=r"(r) : "f"(hi), "f"(lo));
    return r;
}
__device__ __forceinline__ uint32_t pack_f16(float lo, float hi) {
    uint32_t r;
    asm("cvt.rn.f16x2.f32 %0, %1, %2;" : "=r"(r) : "f"(hi), "f"(lo));
    return r;
}
__device__ __forceinline__ uint32_t ex2_h2(uint32_t a) {
    uint32_t r;
    asm("ex2.approx.f16x2 %0, %1;" : "=r"(r) : "r"(a));
    return r;
}
__device__ __forceinline__ uint32_t hadd2(uint32_t a, uint32_t b) {
    uint32_t r;
    asm("add.rn.f16x2 %0, %1, %2;" : "=r"(r) : "r"(a), "r"(b));
    return r;
}
__device__ __forceinline__ float2 h2_to_f2(uint32_t h) {
    __half2 v = *(__half2*)&h;
    return make_float2(__low2float(v), __high2float(v));
}

// ---------------------------------------------------------------------------
// Kernel 0: one-time W/bias convert (wq, bq pre-scaled by QSCALE)
// ---------------------------------------------------------------------------
__global__ __launch_bounds__(256) void setup_kernel(
    const float* __restrict__ wq, const float* __restrict__ bq,
    const float* __restrict__ wk, const float* __restrict__ bk,
    const float* __restrict__ wv, const float* __restrict__ bv)
{
    int idx = blockIdx.x * 256 + threadIdx.x;
    if (idx < 3 * DDIM * CHW) {
        int m = idx >> 12, rc = idx & 4095;
        const float* W = (m == 0) ? wq : (m == 1) ? wk : wv;
        float sc = (m == 0) ? QSCALE : 1.0f;
        g_wb[idx] = __float2bfloat16_rn(W[rc] * sc);
    }
    if (idx < 3 * DDIM) {
        int m = idx >> 6;
        const float* Bp = (m == 0) ? bq : (m == 1) ? bk : bv;
        g_bias[idx] = Bp[idx & 63] * ((m == 0) ? QSCALE : 1.0f);
    }
}

// ---------------------------------------------------------------------------
// Kernel 1: QKV projection on HMMA. 64-token CTAs, grid 256, 128 threads,
// 2 CTAs/SM; x AND W pulled via cp.async (no LDG->STS latency chain).
// ---------------------------------------------------------------------------
#define PXF 0                    // fp32 x [64 c][68 n]       (17408 B)
#define PXB 17408                // bf16 x^T [64 n][72 c] 144B (9216 B)
#define PWB 26624                // bf16 W [3][64 d][72 c] 144B (27648 B)
#define PBI 54272                // fp32 bias [3][64]          (768 B)
#define PSM 55040

__global__ __launch_bounds__(128, 2) void proj_kernel(const float* __restrict__ x)
{
    extern __shared__ char psm[];
    float* xsf = (float*)psm;
    const uint32_t sb = smem_u32(psm);

    const int tid  = threadIdx.x;
    const int w    = tid >> 5;
    const int lane = tid & 31;
    const int g    = lane >> 2;
    const int tc   = lane & 3;
    const int b    = blockIdx.x >> 7;
    const int n0   = (blockIdx.x & 127) * 64;

    // W: exactly 1536 16-B chunks (3*64*64 bf16 = 24576 B); bias: 48 chunks
    #pragma unroll
    for (int j = 0; j < 12; j++) {
        int c = tid + j * 128;                 // 0..1535
        int rrow = c >> 3, c8 = c & 7;
        cp16(sb + PWB + rrow * 144 + c8 * 16, (const char*)g_wb + c * 16);
    }
    if (tid < 48) cp16(sb + PBI + tid * 16, (const char*)g_bias + tid * 16);
    // x tile [64 c][64 n] fp32 (1024 chunks)
    #pragma unroll
    for (int j = 0; j < 8; j++) {
        int c = tid + j * 128;
        int r = c >> 4, c16 = c & 15;
        cp16(sb + PXF + r * 272 + c16 * 16,
             (const char*)x + (((size_t)(b * CHW + r)) * NTOK + n0) * 4 + c16 * 16);
    }
    CP_COMMIT();
    CP_WAIT(0);
    __syncthreads();

    // transpose-convert x -> bf16 [tok][c]
    {
        int n = tid >> 1, ch = (tid & 1) * 32;
        uint32_t u[16];
        #pragma unroll
        for (int j = 0; j < 16; j++)
            u[j] = pack_bf16(xsf[(ch + 2*j) * 68 + n], xsf[(ch + 2*j + 1) * 68 + n]);
        uint4* d4 = (uint4*)(psm + PXB + n * 144 + ch * 2);
        #pragma unroll
        for (int j = 0; j < 4; j++)
            d4[j] = make_uint4(u[4*j], u[4*j+1], u[4*j+2], u[4*j+3]);
    }
    __syncthreads();

    uint32_t af[4][4];
    {
        uint32_t arow = sb + PXB + (w * 16 + (lane & 15)) * 144 + (lane >> 4) * 16;
        #pragma unroll
        for (int kc = 0; kc < 4; kc++)
            ldsm_x4(af[kc], arow + kc * 32);
    }

    const float* biasf = (const float*)(psm + PBI);
    const uint32_t wrow = sb + PWB + (lane & 15) * 144 + (lane >> 4) * 16;

    #pragma unroll
    for (int m = 0; m < 3; m++) {
        float acc[4][2][4];
        #pragma unroll
        for (int i = 0; i < 4; i++)
            #pragma unroll
            for (int s2 = 0; s2 < 2; s2++)
                #pragma unroll
                for (int j = 0; j < 4; j++) acc[i][s2][j] = 0.f;

        #pragma unroll
        for (int nth = 0; nth < 4; nth++) {
            #pragma unroll
            for (int kc = 0; kc < 4; kc++) {
                uint32_t bf[4];
                ldsm_x4(bf, wrow + m * 9216 + nth * 16 * 144 + kc * 32);
                mma_bf16(acc[nth][0], af[kc], bf[0], bf[2]);
                mma_bf16(acc[nth][1], af[kc], bf[1], bf[3]);
            }
        }

        const size_t r0 = (size_t)(b * NTOK + n0 + w * 16 + g) * DDIM;
        const size_t r1 = r0 + 8 * DDIM;
        #pragma unroll
        for (int nth = 0; nth < 4; nth++) {
            #pragma unroll
            for (int s2 = 0; s2 < 2; s2++) {
                int d0 = nth * 16 + s2 * 8 + 2 * tc;
                float bb0 = biasf[m * 64 + d0], bb1 = biasf[m * 64 + d0 + 1];
                float v00 = acc[nth][s2][0] + bb0, v01 = acc[nth][s2][1] + bb1;
                float v10 = acc[nth][s2][2] + bb0, v11 = acc[nth][s2][3] + bb1;
                if (m < 2) {
                    __nv_bfloat16* dst = (m == 0) ? g_q : g_k;
                    *(uint32_t*)(dst + r0 + d0) = pack_bf16(v00, v01);
                    *(uint32_t*)(dst + r1 + d0) = pack_bf16(v10, v11);
                } else {
                    *(uint32_t*)(g_v + r0 + d0) = pack_f16(v00, v01);
                    *(uint32_t*)(g_v + r1 + d0) = pack_f16(v10, v11);
                }
            }
        }
    }
}

// ---------------------------------------------------------------------------
// Kernel 2: balanced persistent FA2 attention (round-9 structure).
// Flush stores f16 partials via in-smem transpose (coalesced [d][n]).
// ---------------------------------------------------------------------------
#define SQ  0
#define SK  18432
#define SV  (18432 * 3)
#define SM_DYN (18432 * 5)

__device__ __forceinline__ void prefetch_kv(uint32_t sb, int item, int tid) {
    const int q  = item >> 6;
    const size_t kbase = (size_t)(q >> 6) * NTOK + (item & 63) * 128;
    const int p  = item & 1;
    const uint4* ks = (const uint4*)(g_k + kbase * DDIM);
    const uint4* vs = (const uint4*)(g_v + kbase * DDIM);
    #pragma unroll
    for (int c = tid, j = 0; j < 4; j++, c += 256) {
        int r = c >> 3, c8 = c & 7;
        uint32_t off = r * ROWB + c8 * 16;
        cp16(sb + SK + p * 18432 + off, ks + c);
        cp16(sb + SV + p * 18432 + off, vs + c);
    }
    CP_COMMIT();
}

// flush Oc/l partials for tile qt (slot derived from bid), f16 O via smem
__device__ __forceinline__ void flush_tile(
    char* smc, int qt, int bid, int tid, int w, int g, int tc,
    float (&Oc)[8][4], float ls0, float ls1)
{
    float a0 = ls0, a1 = ls1;
    a0 += __shfl_xor_sync(0xffffffffu, a0, 1);
    a0 += __shfl_xor_sync(0xffffffffu, a0, 2);
    a1 += __shfl_xor_sync(0xffffffffu, a1, 1);
    a1 += __shfl_xor_sync(0xffffffffu, a1, 2);
    int fb = qt >> 6, fn0 = (qt & 63) * 128;
    int c0 = (NCTA * (64 * qt + 1) - 1) >> 13;
    int slot = bid - c0;
    if (tc == 0) {
        float* lp = g_l + ((size_t)slot * BATCH + fb) * NTOK + fn0 + w * 16 + g;
        lp[0] = a0;
        lp[8] = a1;
    }
    // stage into f16 smem [64 d][136 n] (reuses Q buffer; 17408 B)
    __half* osm = (__half*)(smc + SQ);
    int r0 = w * 16 + g;
    #pragma unroll
    for (int nt = 0; nt < 8; nt++) {
        int d0 = nt * 8 + 2 * tc;
        osm[ d0      * 136 + r0    ] = __float2half_rn(Oc[nt][0]);
        osm[(d0 + 1) * 136 + r0    ] = __float2half_rn(Oc[nt][1]);
        osm[ d0      * 136 + r0 + 8] = __float2half_rn(Oc[nt][2]);
        osm[(d0 + 1) * 136 + r0 + 8] = __float2half_rn(Oc[nt][3]);
    }
    __syncthreads();
    // coalesced write: 64 d-rows x 128 halfwords
    __half* dst = g_oth + ((size_t)slot * BATCH + fb) * DDIM * NTOK + fn0;
    #pragma unroll
    for (int j = 0; j < 4; j++) {
        int c = tid + j * 256;          // 16B chunk id, 1024 total
        int d = c >> 4, o16 = c & 15;
        uint4 v = *(uint4*)&osm[d * 136 + o16 * 8];
        *(uint4*)(dst + d * NTOK + o16 * 8) = v;
    }
}

__global__ __launch_bounds__(256, 2) void attn_kernel()
{
    extern __shared__ char smc[];
    const uint32_t sb = smem_u32(smc);

    const int bid  = blockIdx.x;
    const int tid  = threadIdx.x;
    const int w    = tid >> 5;
    const int lane = tid & 31;
    const int g    = lane >> 2;
    const int tc   = lane & 3;

    const int lo = (bid * NITEMS) / NCTA;
    const int hi = ((bid + 1) * NITEMS) / NCTA;

    prefetch_kv(sb, lo, tid);

    uint32_t qa[4][4];
    float Oc[8][4];
    float ls0, ls1;
    int qt = lo >> 6;

    {
        int b = qt >> 6, n0 = (qt & 63) * 128;
        const uint4* src = (const uint4*)(g_q + ((size_t)(b * NTOK + n0)) * DDIM);
        #pragma unroll
        for (int c = tid, j = 0; j < 4; j++, c += 256) {
            int r = c >> 3, c8 = c & 7;
            *(uint4*)(smc + SQ + r * ROWB + c8 * 16) = src[c];
        }
    }
    __syncthreads();
    {
        uint32_t rowaddr = sb + SQ + (w * 16 + (lane & 15)) * ROWB + (lane >> 4) * 16;
        #pragma unroll
        for (int kc = 0; kc < 4; kc++) ldsm_x4(qa[kc], rowaddr + kc * 32);
    }
    #pragma unroll
    for (int i = 0; i < 8; i++)
        #pragma unroll
        for (int j = 0; j < 4; j++) Oc[i][j] = 0.f;
    ls0 = ls1 = 0.f;

    for (int item = lo; item < hi; item++) {
        CP_WAIT(0);
        __syncthreads();
        if (item + 1 < hi) prefetch_kv(sb, item + 1, tid);

        const int q = item >> 6;
        if (q != qt) {
            flush_tile(smc, qt, bid, tid, w, g, tc, Oc, ls0, ls1);
            __syncthreads();   // osm reads done before Q overwrite
            {
                int b = q >> 6, n0 = (q & 63) * 128;
                const uint4* src = (const uint4*)(g_q + ((size_t)(b * NTOK + n0)) * DDIM);
                #pragma unroll
                for (int c = tid, j = 0; j < 4; j++, c += 256) {
                    int r = c >> 3, c8 = c & 7;
                    *(uint4*)(smc + SQ + r * ROWB + c8 * 16) = src[c];
                }
            }
            __syncthreads();
            {
                uint32_t rowaddr = sb + SQ + (w * 16 + (lane & 15)) * ROWB + (lane >> 4) * 16;
                #pragma unroll
                for (int kc = 0; kc < 4; kc++) ldsm_x4(qa[kc], rowaddr + kc * 32);
            }
            #pragma unroll
            for (int i = 0; i < 8; i++)
                #pragma unroll
                for (int j = 0; j < 4; j++) Oc[i][j] = 0.f;
            ls0 = ls1 = 0.f;
            qt = q;
        }

        const int p = item & 1;
        const uint32_t kb = sb + SK + p * 18432;
        const uint32_t vb = sb + SV + p * 18432;
        const uint32_t lrow = (lane & 15) * ROWB + (lane >> 4) * 16;

        uint32_t s0a = 0u, s1a = 0u;
        #pragma unroll
        for (int h = 0; h < 2; h++) {
            float S[8][4];
            #pragma unroll
            for (int nth = 0; nth < 4; nth++) {
                #pragma unroll
                for (int j = 0; j < 4; j++) { S[2*nth][j] = 0.f; S[2*nth+1][j] = 0.f; }
                #pragma unroll
                for (int kc = 0; kc < 4; kc++) {
                    uint32_t kf[4];
                    ldsm_x4(kf, kb + (h * 4 + nth) * 16 * ROWB + lrow + kc * 32);
                    mma_bf16(S[2*nth],     qa[kc], kf[0], kf[2]);
                    mma_bf16(S[2*nth + 1], qa[kc], kf[1], kf[3]);
                }
            }
            #pragma unroll
            for (int kc2 = 0; kc2 < 4; kc2++) {
                uint32_t pab[4];
                pab[0] = ex2_h2(pack_f16(S[2*kc2][0],   S[2*kc2][1]));
                pab[1] = ex2_h2(pack_f16(S[2*kc2][2],   S[2*kc2][3]));
                pab[2] = ex2_h2(pack_f16(S[2*kc2+1][0], S[2*kc2+1][1]));
                pab[3] = ex2_h2(pack_f16(S[2*kc2+1][2], S[2*kc2+1][3]));
                s0a = hadd2(hadd2(s0a, pab[0]), pab[2]);
                s1a = hadd2(hadd2(s1a, pab[1]), pab[3]);
                #pragma unroll
                for (int ntp = 0; ntp < 4; ntp++) {
                    uint32_t vf[4];
                    ldsm_x4_t(vf, vb + (h * 4 + kc2) * 16 * ROWB + lrow + ntp * 32);
                    mma_f16(Oc[2*ntp],     pab, vf[0], vf[1]);
                    mma_f16(Oc[2*ntp + 1], pab, vf[2], vf[3]);
                }
            }
        }
        {
            float2 f0 = h2_to_f2(s0a), f1 = h2_to_f2(s1a);
            ls0 += f0.x + f0.y;
            ls1 += f1.x + f1.y;
        }
    }

    __syncthreads();   // all warps done with K/V of last item before osm reuse
    flush_tile(smc, qt, bid, tid, w, g, tc, Oc, ls0, ls1);
}

// ---------------------------------------------------------------------------
// Kernel 3: combine slots + normalize + t-reduce (f16 partials, half2 loads).
// ---------------------------------------------------------------------------
__global__ __launch_bounds__(256) void reduce_kernel(float* __restrict__ out)
{
    int idx = blockIdx.x * 256 + threadIdx.x;     // pair index, 0 .. 65535
    int yx = (idx & 511) * 2;
    int d  = (idx >> 9) & 63;
    int b  = idx >> 15;
    const size_t SLOT_O = (size_t)BATCH * DDIM * NTOK;
    const size_t SLOT_L = (size_t)BATCH * NTOK;
    const __half* o0 = g_oth + ((size_t)b * DDIM + d) * NTOK + yx;
    const float*  l0 = g_l   + (size_t)b * NTOK + yx;
    float2 acc = make_float2(0.f, 0.f);
    #pragma unroll
    for (int t = 0; t < TDIM; t++) {
        int n = t * HW;
        float2 ov = make_float2(0.f, 0.f);
        float2 lv = make_float2(0.f, 0.f);
        #pragma unroll
        for (int s = 0; s < NSLOT; s++) {
            __half2 h = *(const __half2*)(o0 + s * SLOT_O + n);
            float2 f = __half22float2(h);
            ov.x += f.x; ov.y += f.y;
            float2 lf = *(const float2*)(l0 + s * SLOT_L + n);
            lv.x += lf.x; lv.y += lf.y;
        }
        acc.x += ov.x / lv.x;
        acc.y += ov.y / lv.y;
    }
    *(float2*)(out + ((size_t)(b * DDIM + d)) * HW + yx) = acc;
}

// ---------------------------------------------------------------------------
extern "C" void kernel_launch(void* const* d_in, const int* in_sizes, int n_in,
                              void* d_out, int out_size)
{
    const float* x  = (const float*)d_in[0];
    const float* wq = (const float*)d_in[1];
    const float* bq = (const float*)d_in[2];
    const float* wk = (const float*)d_in[3];
    const float* bk = (const float*)d_in[4];
    const float* wv = (const float*)d_in[5];
    const float* bv = (const float*)d_in[6];

    cudaFuncSetAttribute(proj_kernel,
                         cudaFuncAttributeMaxDynamicSharedMemorySize, PSM);
    cudaFuncSetAttribute(attn_kernel,
                         cudaFuncAttributeMaxDynamicSharedMemorySize, SM_DYN);

    setup_kernel<<<48, 256>>>(wq, bq, wk, bk, wv, bv);
    proj_kernel<<<BATCH * (NTOK / 64), 128, PSM>>>(x);
    attn_kernel<<<NCTA, 256, SM_DYN>>>();
    reduce_kernel<<<BATCH * DDIM * HW / 512, 256>>>((float*)d_out);
}